// round 11
// baseline (speedup 1.0000x reference)
#include <cuda_runtime.h>
#include <cuda_bf16.h>

#define BB   256
#define T0   1000
#define T1C  1001
#define C1   22
#define C2   25
#define NEP  3
#define NU   (BB*NEP)
#define MM   30
#define TW   128
#define WJ   8

__device__ float g_y1  [BB*C1*T0];
__device__ float g_sig [BB*C2*T1C];
__device__ float g_cov [NU*625];
__device__ float g_V   [NU*MM*325];
__device__ float g_p   [NU*MM];
__device__ float g_xm  [NU*625];
__device__ float g_logQ2[BB*3*324];
__device__ float g_logK2[BB*3*324];
__device__ float g_logV2[BB*3*324];
__device__ float g_feat [BB*513];
__device__ float g_P2 [3*525];
__device__ float g_CZ [3*336];
__device__ float g_E11[3*256];
__device__ float g_mu [3*21];
__device__ float g_E11g3[625];

__device__ __forceinline__ float warp_sum(float v){
    #pragma unroll
    for (int o=16;o;o>>=1) v += __shfl_xor_sync(0xffffffffu, v, o);
    return v;
}

__device__ __forceinline__ void patch_info(int i, int&k, int&pr, int&pc, int&gi){
    if (i<16){ gi=0;k=2;pr=i/4;pc=i%4; }
    else if (i<25){ gi=1;k=3;int p=i-16;pr=p/3;pc=p%3; }
    else if (i<29){ gi=2;k=4;int p=i-25;pr=p/2;pc=p%2; }
    else { gi=3;k=5;pr=0;pc=0; }
}

__device__ void sched_init(unsigned short* sched, int n){
    int m=(n+1)&~1, P=m>>1, R=m-1;
    for (int idx=threadIdx.x; idx<R*P; idx+=blockDim.x){
        int r=idx/P, i=idx%P;
        int j=m-1-i;
        int a=(i==0)?0:(1+(r+i-1)%(m-1));
        int b=1+(r+j-1)%(m-1);
        int p=min(a,b), q=max(a,b);
        sched[idx]=(q<n)? (unsigned short)((p<<8)|q) : (unsigned short)0xFFFF;
    }
    __syncthreads();
}
__device__ void sched_init_w(unsigned short* sched, int n){
    int lane=threadIdx.x&31;
    int m=(n+1)&~1, P=m>>1, R=m-1;
    for (int idx=lane; idx<R*P; idx+=32){
        int r=idx/P, i=idx%P;
        int j=m-1-i;
        int a=(i==0)?0:(1+(r+i-1)%(m-1));
        int b=1+(r+j-1)%(m-1);
        int p=min(a,b), q=max(a,b);
        sched[idx]=(q<n)? (unsigned short)((p<<8)|q) : (unsigned short)0xFFFF;
    }
    __syncwarp();
}
__device__ void tri_init(unsigned short* tri, int n){
    for (int r=threadIdx.x; r<n*(n+1)/2; r+=blockDim.x){
        int i=0, rr=r;
        while (rr>=n-i){ rr-=n-i; i++; }
        tri[r]=(unsigned short)((i<<8)|(i+rr));
    }
    __syncthreads();
}

// Tournament-batched Jacobi with chunked (4-wide) register-batched updates.
// Rotations within a round touch disjoint column pairs, so loads of a chunk
// may be hoisted above its stores — identical arithmetic, better MLP.
__device__ void warp_jacobi(float* A, float* Vv, int n, const unsigned short* sched,
                            int R, int P, float* cb, float* sb, int* pqb, bool preV){
    int lane=threadIdx.x&31;
    if (!preV) for (int e=lane;e<n*n;e+=32) Vv[e]=((e%(n+1))==0)?1.f:0.f;
    float nrm=0.f;
    for (int e=lane;e<n*n;e+=32) nrm+=A[e]*A[e];
    nrm=warp_sum(nrm);
    float thr=nrm*1e-15f+1e-38f;
    __syncwarp();
    for (int sweep=0;sweep<24;sweep++){
        int any=0;
        for (int r=0;r<R;r++){
            bool act=false; int pq=0; float c0=1.f,s0=0.f;
            if (lane<P){
                pq=sched[r*P+lane];
                if (pq!=0xFFFF){
                    int p=pq>>8, q=pq&255;
                    float apq=A[p*n+q];
                    if (apq*apq>thr){
                        act=true;
                        float app=A[p*n+p], aqq=A[q*n+q];
                        float tau=(aqq-app)/(2.f*apq);
                        float t=copysignf(1.f,tau)/(fabsf(tau)+sqrtf(1.f+tau*tau));
                        c0=rsqrtf(1.f+t*t); s0=t*c0;
                    }
                }
            }
            unsigned msk=__ballot_sync(0xffffffffu,act);
            int cnt=__popc(msk);
            if (!cnt) continue;
            any=1;
            if (act){
                int pos=__popc(msk&((1u<<lane)-1u));
                pqb[pos]=pq; cb[pos]=c0; sb[pos]=s0;
            }
            __syncwarp();
            if (lane<n){
                for (int base=0;base<cnt;base+=4){
                    int pqr[4]; float cr_[4], sr_[4], akp[4], akq[4], vkp[4], vkq[4];
                    #pragma unroll
                    for (int j=0;j<4;j++){
                        if (base+j<cnt){
                            pqr[j]=pqb[base+j]; cr_[j]=cb[base+j]; sr_[j]=sb[base+j];
                            int p=pqr[j]>>8, q=pqr[j]&255;
                            akp[j]=A[lane*n+p];  akq[j]=A[lane*n+q];
                            vkp[j]=Vv[lane*n+p]; vkq[j]=Vv[lane*n+q];
                        }
                    }
                    #pragma unroll
                    for (int j=0;j<4;j++){
                        if (base+j<cnt){
                            int p=pqr[j]>>8, q=pqr[j]&255;
                            A[lane*n+p]=cr_[j]*akp[j]-sr_[j]*akq[j];
                            A[lane*n+q]=sr_[j]*akp[j]+cr_[j]*akq[j];
                            Vv[lane*n+p]=cr_[j]*vkp[j]-sr_[j]*vkq[j];
                            Vv[lane*n+q]=sr_[j]*vkp[j]+cr_[j]*vkq[j];
                        }
                    }
                }
            }
            __syncwarp();
            if (lane<n){
                for (int base=0;base<cnt;base+=4){
                    int pqr[4]; float cr_[4], sr_[4], apk[4], aqk[4];
                    #pragma unroll
                    for (int j=0;j<4;j++){
                        if (base+j<cnt){
                            pqr[j]=pqb[base+j]; cr_[j]=cb[base+j]; sr_[j]=sb[base+j];
                            int p=pqr[j]>>8, q=pqr[j]&255;
                            apk[j]=A[p*n+lane]; aqk[j]=A[q*n+lane];
                        }
                    }
                    #pragma unroll
                    for (int j=0;j<4;j++){
                        if (base+j<cnt){
                            int p=pqr[j]>>8, q=pqr[j]&255;
                            A[p*n+lane]=cr_[j]*apk[j]-sr_[j]*aqk[j];
                            A[q*n+lane]=sr_[j]*apk[j]+cr_[j]*aqk[j];
                        }
                    }
                }
            }
            __syncwarp();
        }
        if (!any) break;
    }
    __syncwarp();
}

__device__ __forceinline__ void eigh4_plain(const float* m, float* a, float* v){
    #pragma unroll
    for (int i=0;i<16;i++){ a[i]=m[i]; v[i]=((i%5)==0)?1.f:0.f; }
    float nrm=0.f;
    #pragma unroll
    for (int i=0;i<16;i++) nrm+=a[i]*a[i];
    float thr=nrm*1e-15f+1e-38f;
    for (int sw=0;sw<10;sw++){
        bool rot=false;
        #pragma unroll
        for (int p=0;p<3;p++){
            #pragma unroll
            for (int q=p+1;q<4;q++){
                float apq=a[p*4+q];
                if (apq*apq>thr){
                    rot=true;
                    float app=a[p*5], aqq=a[q*5];
                    float tau=(aqq-app)/(2.f*apq);
                    float t=copysignf(1.f,tau)/(fabsf(tau)+sqrtf(1.f+tau*tau));
                    float c=rsqrtf(1.f+t*t), s=t*c;
                    #pragma unroll
                    for (int k2=0;k2<4;k2++){
                        float akp=a[k2*4+p], akq=a[k2*4+q];
                        a[k2*4+p]=c*akp-s*akq; a[k2*4+q]=s*akp+c*akq;
                        float vkp=v[k2*4+p], vkq=v[k2*4+q];
                        v[k2*4+p]=c*vkp-s*vkq; v[k2*4+q]=s*vkp+c*vkq;
                    }
                    #pragma unroll
                    for (int k2=0;k2<4;k2++){
                        float apk=a[p*4+k2], aqk=a[q*4+k2];
                        a[p*4+k2]=c*apk-s*aqk; a[q*4+k2]=s*apk+c*aqk;
                    }
                }
            }
        }
        if (!rot) break;
    }
}

__device__ __forceinline__ void eigh4_log(const float* m, float* out){
    float a[16], v[16];
    eigh4_plain(m,a,v);
    float fw[4];
    #pragma unroll
    for (int i=0;i<4;i++) fw[i]=logf(fmaxf(a[i*5],1e-9f));
    #pragma unroll
    for (int i=0;i<16;i++){
        int r2=i/4, c2=i%4;
        float acc=0.f;
        #pragma unroll
        for (int k2=0;k2<4;k2++) acc+=v[r2*4+k2]*fw[k2]*v[c2*4+k2];
        out[i]=acc;
    }
}

__global__ void k_prep(const float* __restrict__ sv0,const float* __restrict__ sv1,
                       const float* __restrict__ sv2,const float* __restrict__ sv3){
    __shared__ float shp[3][1560];
    __shared__ unsigned short ssch[3][231];
    __shared__ float cbs[3][16], sbs[3][16];
    __shared__ int pqs[3][16];
    int warp=threadIdx.x>>5, lane=threadIdx.x&31;
    if (warp==3){
        for (int e=lane;e<625;e+=32){
            int i=e/25, j=e%25;
            float acc=0.f;
            for (int a=0;a<25;a++) acc+=sv3[i*25+a]*(4e-6f*(1.f+a))*sv3[j*25+a];
            g_E11g3[e]=acc;
        }
        return;
    }
    const float* sv=(warp==0?sv0:warp==1?sv1:sv2);
    const int KAP=(warp==0?4:warp==1?9:16);
    const int R=25-KAP;
    float* Wp=shp[warp];
    float* F =Wp+525;
    float* Z =F+441;
    float* Bm=Z+441;
    for (int e=lane;e<KAP*KAP;e+=32){
        int i=e/KAP, j=e%KAP;
        float acc=0.f;
        for (int a=0;a<25;a++) acc+=sv[i*25+a]*(4e-6f*(1.f+a))*sv[j*25+a];
        g_E11[warp*256+i*16+j]=acc;
    }
    __syncwarp();
    int rc=0;
    for (int cand=0; cand<25 && rc<R; cand++){
        float v=(lane==cand)?1.f:0.f;
        for (int pass=0;pass<2;pass++){
            for (int i=0;i<KAP;i++){
                float w=(lane<25)?sv[i*25+lane]:0.f;
                float d=warp_sum(v*w); v-=d*w;
            }
            for (int i=0;i<rc;i++){
                float w=(lane<25)?Wp[i*25+lane]:0.f;
                float d=warp_sum(v*w); v-=d*w;
            }
        }
        float nn=warp_sum(v*v);
        if (nn>1e-4f){
            float inv=rsqrtf(nn);
            if (lane<25) Wp[rc*25+lane]=v*inv;
            rc++;
        }
        __syncwarp();
    }
    for (int e=lane;e<R*R;e+=32){
        int m2=e/R, n2=e%R;
        float acc=0.f;
        for (int a=0;a<25;a++) acc+=Wp[m2*25+a]*(4e-6f*(1.f+a))*Wp[n2*25+a];
        F[e]=acc;
    }
    sched_init_w(ssch[warp],R);
    int m=(R+1)&~1;
    warp_jacobi(F,Z,R,ssch[warp],m-1,m>>1,cbs[warp],sbs[warp],pqs[warp],false);
    if (lane<R) g_mu[warp*21+lane]=F[lane*(R+1)];
    __syncwarp();
    for (int e=lane;e<25*R;e+=32){
        int a=e/R, m2=e%R;
        float acc=0.f;
        for (int t=0;t<R;t++) acc+=Wp[t*25+a]*Z[t*R+m2];
        g_P2[warp*525+a*21+m2]=acc;
    }
    for (int e=lane;e<KAP*R;e+=32){
        int i=e/R, t=e%R;
        float acc=0.f;
        for (int a=0;a<25;a++) acc+=sv[i*25+a]*(4e-6f*(1.f+a))*Wp[t*25+a];
        Bm[e]=acc;
    }
    __syncwarp();
    for (int e=lane;e<KAP*R;e+=32){
        int i=e/R, m2=e%R;
        float acc=0.f;
        for (int t=0;t<R;t++) acc+=Bm[i*R+t]*Z[t*R+m2];
        g_CZ[warp*336+i*21+m2]=acc;
    }
}

__global__ void k_conv1(const float* __restrict__ x, const float* __restrict__ w,
                        const float* __restrict__ cb, const float* __restrict__ bg,
                        const float* __restrict__ bb, const float* __restrict__ bm,
                        const float* __restrict__ bv){
    __shared__ float sw[C1*C1];
    __shared__ float ssc[C1], ssh[C1];
    int tid=threadIdx.x;
    for (int i=tid;i<C1*C1;i+=blockDim.x) sw[i]=w[i];
    if (tid<C1){
        float sc=bg[tid]*rsqrtf(bv[tid]+1e-5f);
        ssc[tid]=sc; ssh[tid]=bb[tid]+(cb[tid]-bm[tid])*sc;
    }
    __syncthreads();
    int b=blockIdx.y; int t=blockIdx.x*blockDim.x+tid;
    if (t>=T0) return;
    float xv[C1];
    #pragma unroll
    for (int h=0;h<C1;h++) xv[h]=x[(b*C1+h)*T0+t];
    #pragma unroll 1
    for (int o=0;o<C1;o++){
        float acc=0.f;
        #pragma unroll
        for (int h=0;h<C1;h++) acc+=xv[h]*sw[o*C1+h];
        g_y1[(b*C1+o)*T0+t]=acc*ssc[o]+ssh[o];
    }
}

__global__ void k_conv2(const float* __restrict__ w2, const float* __restrict__ cb,
                        const float* __restrict__ bg, const float* __restrict__ bb,
                        const float* __restrict__ bm, const float* __restrict__ bv){
    __shared__ float sw[C2*C1*12];
    __shared__ float sy[C1*(TW+12)];
    __shared__ float ssc[C2], ssh[C2];
    int tid=threadIdx.x;
    for (int i=tid;i<C2*C1*12;i+=TW) sw[i]=w2[i];
    if (tid<C2){
        float sc=bg[tid]*rsqrtf(bv[tid]+1e-5f);
        ssc[tid]=sc; ssh[tid]=bb[tid]+(cb[tid]-bm[tid])*sc;
    }
    int b=blockIdx.y; int t0=blockIdx.x*TW;
    for (int i=tid;i<C1*(TW+12);i+=TW){
        int c=i/(TW+12), u=i%(TW+12);
        int tt=t0-6+u;
        sy[i]=(tt>=0 && tt<T0)? g_y1[(b*C1+c)*T0+tt] : 0.f;
    }
    __syncthreads();
    int t=t0+tid;
    if (t>=T1C) return;
    float acc[C2];
    #pragma unroll
    for (int o=0;o<C2;o++) acc[o]=0.f;
    for (int c=0;c<C1;c++){
        float yv[12];
        #pragma unroll
        for (int kk=0;kk<12;kk++) yv[kk]=sy[c*(TW+12)+tid+kk];
        #pragma unroll 1
        for (int o=0;o<C2;o++){
            float a=acc[o];
            #pragma unroll
            for (int kk=0;kk<12;kk++) a+=yv[kk]*sw[(o*C1+c)*12+kk];
            acc[o]=a;
        }
    }
    #pragma unroll 1
    for (int o=0;o<C2;o++) g_sig[(b*C2+o)*T1C+t]=acc[o]*ssc[o]+ssh[o];
}

__global__ void k_cov(){
    __shared__ float s[C2*334];
    __shared__ float cc[325];
    __shared__ float tr_s;
    int u=blockIdx.x, b=u/NEP, e=u%NEP;
    int off=e*334; int L=(e==2)?333:334;
    int tid=threadIdx.x;
    for (int idx=tid; idx<C2*L; idx+=256){
        int c=idx/L, t=idx%L;
        s[c*334+t]=g_sig[(b*C2+c)*T1C+off+t];
    }
    __syncthreads();
    if (tid<C2){
        float acc=0.f;
        for (int t=0;t<L;t++) acc+=s[tid*334+t];
        float mean=acc/(float)L;
        for (int t=0;t<L;t++) s[tid*334+t]-=mean;
    }
    __syncthreads();
    for (int r=tid;r<325;r+=256){
        int i=0, rr=r;
        while (rr>=C2-i){ rr-=C2-i; i++; }
        int j=i+rr;
        float acc=0.f;
        for (int t=0;t<L;t++) acc+=s[i*334+t]*s[j*334+t];
        cc[r]=acc/(float)(L-1);
    }
    __syncthreads();
    if (tid==0){
        float tr=0.f;
        for (int i=0;i<C2;i++) tr+=cc[i*C2 - i*(i-1)/2];
        tr_s=tr;
    }
    __syncthreads();
    float inv=1.f/tr_s;
    float* dst=g_cov+u*625;
    for (int e2=tid;e2<625;e2+=256){
        int i=e2/25, j=e2%25;
        int ii=min(i,j), jj=max(i,j);
        float v=cc[ii*C2 - ii*(ii-1)/2 + (jj-ii)]*inv;
        if (i==j) v+=1e-5f;
        dst[e2]=v;
    }
}

__global__ void k_qk(const float* __restrict__ sk0,const float* __restrict__ sk1,
                     const float* __restrict__ sk2,const float* __restrict__ sk3,
                     const float* __restrict__ sq3){
    __shared__ float scov[4][625];
    __shared__ float sK[4][31*16];
    int warp=threadIdx.x>>5, lane=threadIdx.x&31;
    int u=blockIdx.x*4+warp;
    const float* cov=g_cov+u*625;
    for (int e=lane;e<625;e+=32) scov[warp][e]=cov[e];
    __syncwarp();
    if (lane<31){
        int i=(lane==30)?29:lane;
        int k,pr,pc,gi; patch_info(i,k,pr,pc,gi);
        int kk=k*k;
        const float* W=(lane==30)? sq3 : (gi==0?sk0:gi==1?sk1:gi==2?sk2:sk3);
        float Km[16];
        #pragma unroll
        for (int e=0;e<16;e++) Km[e]=0.f;
        for (int c=0;c<kk;c++){
            int ic=(pr+c/k)*5 + pc + c%k;
            float sa[4]={0.f,0.f,0.f,0.f};
            for (int r=0;r<kk;r++){
                int ir=(pr+r/k)*5 + pc + r%k;
                float xx=scov[warp][ir*25+ic];
                #pragma unroll
                for (int a=0;a<4;a++) sa[a]+=W[r*4+a]*xx;
            }
            #pragma unroll
            for (int a=0;a<4;a++)
                #pragma unroll
                for (int b2=0;b2<4;b2++) Km[a*4+b2]+=sa[a]*W[c*4+b2];
        }
        #pragma unroll
        for (int d=0;d<4;d++) Km[d*5]+=2.5e-5f*(1.f+d);
        float logm[16];
        eigh4_log(Km, logm);
        #pragma unroll
        for (int e=0;e<16;e++) sK[warp][lane*16+e]=logm[e];
    }
    __syncwarp();
    float scval=-1e30f;
    if (lane<30){
        float kn=0.f,cr=0.f,qn=0.f;
        #pragma unroll
        for (int e=0;e<16;e++){
            float a=sK[warp][lane*16+e], q=sK[warp][30*16+e];
            kn+=a*a; cr+=a*q; qn+=q*q;
        }
        float E=fmaxf(kn+qn-2.f*cr,0.f);
        scval=1.f/(1.f+log1pf(E));
    }
    float mx=scval;
    #pragma unroll
    for (int o=16;o;o>>=1) mx=fmaxf(mx,__shfl_xor_sync(0xffffffffu,mx,o));
    float ev=(lane<30)?expf(scval-mx):0.f;
    float sm=warp_sum(ev);
    if (lane<30) g_p[u*30+lane]=ev/sm;
}

template<int KAP>
__device__ void logv_mid(float* A, float* V, int gi, const float* __restrict__ sv,
                         const float* __restrict__ cov, int k, int pr, int pc,
                         const unsigned short* schedS, const unsigned short* sched25,
                         float* cb, float* sb, int* pqb){
    const int lane=threadIdx.x&31;
    const int R=25-KAP;
    const float* E11=g_E11+gi*256;
    const float* mu =g_mu +gi*21;
    const float* P2 =g_P2 +gi*525;
    const float* CZ =g_CZ +gi*336;
    for (int e=lane;e<KAP*KAP;e+=32){
        int r=e/KAP, c=e%KAP;
        int ir=(pr+r/k)*5+pc+r%k;
        int ic=(pr+c/k)*5+pc+c%k;
        A[e]=cov[ir*25+ic]+E11[r*16+c];
    }
    __syncwarp();
    const int m=(KAP+1)&~1;
    warp_jacobi(A,V,KAP,schedS,m-1,m>>1,cb,sb,pqb,false);
    float Yc[KAP];
    float lam=0.f;
    if (lane<KAP){
        #pragma unroll
        for (int t=0;t<KAP;t++) Yc[t]=V[t*KAP+lane];
        lam=A[lane*(KAP+1)];
    }
    __syncwarp();
    for (int e=lane;e<625;e+=32) A[e]=0.f;
    __syncwarp();
    if (lane<KAP){
        A[lane*26]=lam;
        #pragma unroll 1
        for (int mm2=0;mm2<R;mm2++){
            float g=0.f;
            #pragma unroll
            for (int t=0;t<KAP;t++) g+=Yc[t]*CZ[t*21+mm2];
            A[lane*25+(KAP+mm2)]=g;
            A[(KAP+mm2)*25+lane]=g;
        }
    } else if (lane<25){
        A[lane*26]=mu[lane-KAP];
    }
    for (int e=lane;e<25*R;e+=32){
        int a=e/R, mm2=e%R;
        V[a*25+KAP+mm2]=P2[a*21+mm2];
    }
    __syncwarp();
    if (lane<KAP){
        #pragma unroll 1
        for (int a=0;a<25;a++){
            float val=0.f;
            #pragma unroll
            for (int i2=0;i2<KAP;i2++) val+=sv[i2*25+a]*Yc[i2];
            V[a*25+lane]=val;
        }
    }
    __syncwarp();
    warp_jacobi(A,V,25,sched25,25,13,cb,sb,pqb,true);
}

__global__ void k_logV(const float* __restrict__ sv0,const float* __restrict__ sv1,
                       const float* __restrict__ sv2,const float* __restrict__ sv3){
    __shared__ float sh[WJ][1250];
    __shared__ float scb[WJ][16], ssb[WJ][16];
    __shared__ int spq[WJ][16];
    __shared__ float sd[WJ][25];
    __shared__ unsigned short sched25[325];
    __shared__ unsigned short sched9[45];
    __shared__ unsigned short sched16[120];
    __shared__ unsigned short tri25[325];
    sched_init(sched25,25);
    sched_init(sched9,9);
    sched_init(sched16,16);
    tri_init(tri25,25);
    int warp=threadIdx.x>>5, lane=threadIdx.x&31;
    int gw=blockIdx.x*WJ+warp;
    if (gw>=NU*MM) return;
    int u=gw/MM, i=gw%MM;
    float* A=sh[warp]; float* V=A+625;
    int k,pr,pc,gi; patch_info(i,k,pr,pc,gi);
    const float* cov=g_cov+u*625;
    if (gi==0){
        float sm4[16], av[16], vv[16];
        #pragma unroll
        for (int e=0;e<16;e++){
            int r=e>>2, c=e&3;
            int ir=(pr+(r>>1))*5+pc+(r&1);
            int ic=(pr+(c>>1))*5+pc+(c&1);
            sm4[e]=cov[ir*25+ic]+g_E11[r*16+c];
        }
        eigh4_plain(sm4,av,vv);
        for (int e=lane;e<625;e+=32){
            int a=e/25, b=e%25;
            float val=0.f;
            if (a==b) val=(a<4)? av[a*5] : g_mu[a-4];
            else if (a<4 && b>=4){
                #pragma unroll
                for (int t=0;t<4;t++) val+=vv[t*4+a]*g_CZ[t*21+(b-4)];
            } else if (b<4 && a>=4){
                #pragma unroll
                for (int t=0;t<4;t++) val+=vv[t*4+b]*g_CZ[t*21+(a-4)];
            }
            A[e]=val;
        }
        for (int e=lane;e<625;e+=32){
            int a=e/25, j=e%25;
            float val;
            if (j<4){
                val=0.f;
                #pragma unroll
                for (int i2=0;i2<4;i2++) val+=sv0[i2*25+a]*vv[i2*4+j];
            } else val=g_P2[a*21+(j-4)];
            V[e]=val;
        }
        __syncwarp();
        warp_jacobi(A,V,25,sched25,25,13,scb[warp],ssb[warp],spq[warp],true);
    } else if (gi==1){
        logv_mid<9>(A,V,1,sv1,cov,k,pr,pc,sched9,sched25,scb[warp],ssb[warp],spq[warp]);
    } else if (gi==2){
        logv_mid<16>(A,V,2,sv2,cov,k,pr,pc,sched16,sched25,scb[warp],ssb[warp],spq[warp]);
    } else {
        for (int e=lane;e<625;e+=32) A[e]=cov[e]+g_E11g3[e];
        for (int e=lane;e<625;e+=32){
            int a=e/25, j=e%25;
            V[e]=sv3[j*25+a];
        }
        __syncwarp();
        warp_jacobi(A,V,25,sched25,25,13,scb[warp],ssb[warp],spq[warp],true);
    }
    if (lane<25) sd[warp][lane]=logf(fmaxf(A[lane*26],1e-9f));
    __syncwarp();
    for (int e=lane;e<625;e+=32) A[e]=V[e]*sd[warp][e%25];
    __syncwarp();
    float* out=g_V+(size_t)gw*325;
    for (int r=lane;r<325;r+=32){
        int ij=tri25[r]; int a=ij>>8, b=ij&255;
        float acc=0.f;
        #pragma unroll 5
        for (int kx=0;kx<25;kx++) acc+=A[a*25+kx]*V[b*25+kx];
        out[r]=acc;
    }
}

__global__ void k_att1(){
    __shared__ float sh[WJ][1250];
    __shared__ float scb[WJ][16], ssb[WJ][16];
    __shared__ int spq[WJ][16];
    __shared__ float sd[WJ][25];
    __shared__ unsigned short sched[325];
    __shared__ unsigned short tri25[325];
    __shared__ float pp[WJ][30];
    sched_init(sched,25);
    tri_init(tri25,25);
    int warp=threadIdx.x>>5, lane=threadIdx.x&31;
    int u=blockIdx.x*WJ+warp;
    if (u>=NU) return;
    float* A=sh[warp]; float* V=A+625;
    if (lane<30) pp[warp][lane]=g_p[u*30+lane];
    __syncwarp();
    const float* Vb=g_V+(size_t)u*30*325;
    for (int r=lane;r<325;r+=32){
        float acc=0.f;
        #pragma unroll 5
        for (int i=0;i<30;i++) acc+=pp[warp][i]*Vb[(size_t)i*325+r];
        int ij=tri25[r]; int a=ij>>8, b=ij&255;
        A[a*25+b]=acc; A[b*25+a]=acc;
    }
    __syncwarp();
    warp_jacobi(A,V,25,sched,25,13,scb[warp],ssb[warp],spq[warp],false);
    if (lane<25) sd[warp][lane]=fmaxf(expf(A[lane*26]),1e-4f);
    __syncwarp();
    for (int e=lane;e<625;e+=32) A[e]=V[e]*sd[warp][e%25];
    __syncwarp();
    float* dst=g_xm+u*625;
    for (int r=lane;r<325;r+=32){
        int ij=tri25[r]; int a=ij>>8, b=ij&255;
        float acc=0.f;
        #pragma unroll 5
        for (int kx=0;kx<25;kx++) acc+=A[a*25+kx]*V[b*25+kx];
        dst[a*25+b]=acc; dst[b*25+a]=acc;
    }
}

__global__ void k_s2log(const float* __restrict__ mq,const float* __restrict__ mk,
                        const float* __restrict__ mv){
    __shared__ float sh[WJ][1250];
    __shared__ float scb[WJ][16], ssb[WJ][16];
    __shared__ int spq[WJ][16];
    __shared__ float sd[WJ][18];
    __shared__ unsigned short sched[153];
    __shared__ unsigned short tri18[171];
    sched_init(sched,18);
    tri_init(tri18,18);
    int warp=threadIdx.x>>5, lane=threadIdx.x&31;
    int id=blockIdx.x*WJ+warp;
    if (id>=BB*9) return;
    int b=id/9, rem=id%9, t=rem/3, c=rem%3;
    float* A=sh[warp]; float* V=A+625;
    const float* W=(c==0?mq:(c==1?mk:mv));
    const float* X=g_xm+(b*3+t)*625;
    for (int e=lane;e<450;e+=32){
        int r=e/18, a=e%18;
        float acc=0.f;
        for (int cc=0;cc<25;cc++) acc+=X[r*25+cc]*W[cc*18+a];
        V[e]=acc;
    }
    __syncwarp();
    for (int e=lane;e<324;e+=32){
        int a=e/18, bb=e%18;
        float acc=0.f;
        for (int r=0;r<25;r++) acc+=W[r*18+a]*V[r*18+bb];
        A[e]=acc;
    }
    __syncwarp();
    warp_jacobi(A,V,18,sched,17,9,scb[warp],ssb[warp],spq[warp],false);
    if (lane<18) sd[warp][lane]=logf(fmaxf(A[lane*19],1e-9f));
    __syncwarp();
    for (int e=lane;e<324;e+=32) A[e]=V[e]*sd[warp][e%18];
    __syncwarp();
    float* dst=(c==0?g_logQ2:(c==1?g_logK2:g_logV2))+(b*3+t)*324;
    for (int r=lane;r<171;r+=32){
        int ij=tri18[r]; int a=ij>>8, bb=ij&255;
        float acc=0.f;
        #pragma unroll 6
        for (int kx=0;kx<18;kx++) acc+=A[a*18+kx]*V[bb*18+kx];
        dst[a*18+bb]=acc; dst[bb*18+a]=acc;
    }
}

__global__ void k_s2att(){
    __shared__ float sh[WJ][1250];
    __shared__ float scb[WJ][16], ssb[WJ][16];
    __shared__ int spq[WJ][16];
    __shared__ float sd[WJ][18];
    __shared__ unsigned short sched[153];
    __shared__ unsigned short tri18[171];
    sched_init(sched,18);
    tri_init(tri18,18);
    int warp=threadIdx.x>>5, lane=threadIdx.x&31;
    int id=blockIdx.x*WJ+warp;
    if (id>=BB*3) return;
    int b=id/3, j=id%3;
    float* A=sh[warp]; float* V=A+625;
    const float* lQ=g_logQ2+(b*3+j)*324;
    float qn=0.f;
    for (int e=lane;e<324;e+=32){ float v=lQ[e]; qn+=v*v; }
    qn=warp_sum(qn);
    float p3[3];
    #pragma unroll
    for (int i=0;i<3;i++){
        const float* lK=g_logK2+(b*3+i)*324;
        float kn=0.f, cr=0.f;
        for (int e=lane;e<324;e+=32){ float a=lK[e], q=lQ[e]; kn+=a*a; cr+=a*q; }
        kn=warp_sum(kn); cr=warp_sum(cr);
        float E=fmaxf(kn+qn-2.f*cr,0.f);
        p3[i]=1.f/(1.f+log1pf(E));
    }
    float mx=fmaxf(p3[0],fmaxf(p3[1],p3[2]));
    float sm=0.f;
    #pragma unroll
    for (int i=0;i<3;i++){ p3[i]=expf(p3[i]-mx); sm+=p3[i]; }
    #pragma unroll
    for (int i=0;i<3;i++) p3[i]/=sm;
    for (int e=lane;e<324;e+=32){
        float acc=0.f;
        #pragma unroll
        for (int i=0;i<3;i++) acc+=p3[i]*g_logV2[(b*3+i)*324+e];
        A[e]=acc;
    }
    __syncwarp();
    warp_jacobi(A,V,18,sched,17,9,scb[warp],ssb[warp],spq[warp],false);
    if (lane<18) sd[warp][lane]=fmaxf(A[lane*19],-9.210340371976184f);
    __syncwarp();
    for (int e=lane;e<324;e+=32) A[e]=V[e]*sd[warp][e%18];
    __syncwarp();
    for (int r=lane;r<171;r+=32){
        int ij=tri18[r]; int ii=ij>>8, jj=ij&255;
        float acc=0.f;
        #pragma unroll 6
        for (int kx=0;kx<18;kx++) acc+=A[ii*18+kx]*V[jj*18+kx];
        float coef=(ii==jj)?1.f:1.41421356237309515f;
        g_feat[b*513 + j*171 + r]=acc*coef;
    }
}

__global__ void k_head(const float* __restrict__ lw, const float* __restrict__ lb,
                       float* __restrict__ out){
    int b=blockIdx.x; int o=threadIdx.x>>5; int lane=threadIdx.x&31;
    if (o>=4) return;
    float acc=0.f;
    for (int r=lane;r<513;r+=32) acc+=g_feat[b*513+r]*lw[o*513+r];
    acc=warp_sum(acc);
    if (lane==0) out[b*4+o]=acc+lb[o];
}

extern "C" void kernel_launch(void* const* d_in, const int* in_sizes, int n_in,
                              void* d_out, int out_size){
    const float* x   =(const float*)d_in[0];
    const float* c1w =(const float*)d_in[1];
    const float* c1b =(const float*)d_in[2];
    const float* bn1g=(const float*)d_in[3];
    const float* bn1b=(const float*)d_in[4];
    const float* bn1m=(const float*)d_in[5];
    const float* bn1v=(const float*)d_in[6];
    const float* c2w =(const float*)d_in[7];
    const float* c2b =(const float*)d_in[8];
    const float* bn2g=(const float*)d_in[9];
    const float* bn2b=(const float*)d_in[10];
    const float* bn2m=(const float*)d_in[11];
    const float* bn2v=(const float*)d_in[12];
    bool inter = (in_sizes[14]==16);
    const float *sk[4], *sv[4], *sq3p;
    if (inter){
        sq3p=(const float*)d_in[13+3*3];
        for (int g=0; g<4; g++){
            sk[g]=(const float*)d_in[14+3*g];
            sv[g]=(const float*)d_in[15+3*g];
        }
    } else {
        sq3p=(const float*)d_in[16];
        for (int g=0; g<4; g++){
            sk[g]=(const float*)d_in[17+g];
            sv[g]=(const float*)d_in[21+g];
        }
    }
    const float* mq=(const float*)d_in[25];
    const float* mk=(const float*)d_in[26];
    const float* mv=(const float*)d_in[27];
    const float* lw=(const float*)d_in[28];
    const float* lb=(const float*)d_in[29];

    k_prep <<<1,128>>>(sv[0],sv[1],sv[2],sv[3]);
    k_conv1<<<dim3(8,BB),128>>>(x,c1w,c1b,bn1g,bn1b,bn1m,bn1v);
    k_conv2<<<dim3(8,BB),128>>>(c2w,c2b,bn2g,bn2b,bn2m,bn2v);
    k_cov  <<<NU,256>>>();
    k_qk   <<<NU/4,128>>>(sk[0],sk[1],sk[2],sk[3],sq3p);
    k_logV <<<(NU*MM+WJ-1)/WJ,WJ*32>>>(sv[0],sv[1],sv[2],sv[3]);
    k_att1 <<<(NU+WJ-1)/WJ,WJ*32>>>();
    k_s2log<<<(BB*9+WJ-1)/WJ,WJ*32>>>(mq,mk,mv);
    k_s2att<<<(BB*3+WJ-1)/WJ,WJ*32>>>();
    k_head <<<BB,128>>>(lw,lb,(float*)d_out);
}

// round 12
// speedup vs baseline: 1.4058x; 1.4058x over previous
#include <cuda_runtime.h>
#include <cuda_bf16.h>

#define BB   256
#define T0   1000
#define T1C  1001
#define C1   22
#define C2   25
#define NEP  3
#define NU   (BB*NEP)
#define MM   30
#define TW   128
#define WJ   8

__device__ float g_y1  [BB*C1*T0];
__device__ float g_sig [BB*C2*T1C];
__device__ float g_cov [NU*625];
__device__ float g_V   [NU*MM*325];
__device__ float g_p   [NU*MM];
__device__ float g_xm  [NU*625];
__device__ float g_logQ2[BB*3*324];
__device__ float g_logK2[BB*3*324];
__device__ float g_logV2[BB*3*324];
__device__ float g_feat [BB*513];
__device__ float g_P2 [3*525];
__device__ float g_CZ [3*336];
__device__ float g_E11[3*256];
__device__ float g_mu [3*21];
__device__ float g_E11g3[625];

__device__ __forceinline__ float warp_sum(float v){
    #pragma unroll
    for (int o=16;o;o>>=1) v += __shfl_xor_sync(0xffffffffu, v, o);
    return v;
}

__device__ __forceinline__ void patch_info(int i, int&k, int&pr, int&pc, int&gi){
    if (i<16){ gi=0;k=2;pr=i/4;pc=i%4; }
    else if (i<25){ gi=1;k=3;int p=i-16;pr=p/3;pc=p%3; }
    else if (i<29){ gi=2;k=4;int p=i-25;pr=p/2;pc=p%2; }
    else { gi=3;k=5;pr=0;pc=0; }
}

__device__ void sched_init(unsigned short* sched, int n){
    int m=(n+1)&~1, P=m>>1, R=m-1;
    for (int idx=threadIdx.x; idx<R*P; idx+=blockDim.x){
        int r=idx/P, i=idx%P;
        int j=m-1-i;
        int a=(i==0)?0:(1+(r+i-1)%(m-1));
        int b=1+(r+j-1)%(m-1);
        int p=min(a,b), q=max(a,b);
        sched[idx]=(q<n)? (unsigned short)((p<<8)|q) : (unsigned short)0xFFFF;
    }
    __syncthreads();
}
__device__ void sched_init_w(unsigned short* sched, int n){
    int lane=threadIdx.x&31;
    int m=(n+1)&~1, P=m>>1, R=m-1;
    for (int idx=lane; idx<R*P; idx+=32){
        int r=idx/P, i=idx%P;
        int j=m-1-i;
        int a=(i==0)?0:(1+(r+i-1)%(m-1));
        int b=1+(r+j-1)%(m-1);
        int p=min(a,b), q=max(a,b);
        sched[idx]=(q<n)? (unsigned short)((p<<8)|q) : (unsigned short)0xFFFF;
    }
    __syncwarp();
}
__device__ void tri_init(unsigned short* tri, int n){
    for (int r=threadIdx.x; r<n*(n+1)/2; r+=blockDim.x){
        int i=0, rr=r;
        while (rr>=n-i){ rr-=n-i; i++; }
        tri[r]=(unsigned short)((i<<8)|(i+rr));
    }
    __syncthreads();
}

// Tournament-batched Jacobi (R10-proven structure; threshold relaxed 1e-15 -> 1e-14).
__device__ void warp_jacobi(float* A, float* Vv, int n, const unsigned short* sched,
                            int R, int P, float* cb, float* sb, int* pqb, bool preV){
    int lane=threadIdx.x&31;
    if (!preV) for (int e=lane;e<n*n;e+=32) Vv[e]=((e%(n+1))==0)?1.f:0.f;
    float nrm=0.f;
    for (int e=lane;e<n*n;e+=32) nrm+=A[e]*A[e];
    nrm=warp_sum(nrm);
    float thr=nrm*1e-14f+1e-38f;
    __syncwarp();
    for (int sweep=0;sweep<24;sweep++){
        int any=0;
        for (int r=0;r<R;r++){
            bool act=false; int pq=0; float c0=1.f,s0=0.f;
            if (lane<P){
                pq=sched[r*P+lane];
                if (pq!=0xFFFF){
                    int p=pq>>8, q=pq&255;
                    float apq=A[p*n+q];
                    if (apq*apq>thr){
                        act=true;
                        float app=A[p*n+p], aqq=A[q*n+q];
                        float tau=(aqq-app)/(2.f*apq);
                        float t=copysignf(1.f,tau)/(fabsf(tau)+sqrtf(1.f+tau*tau));
                        c0=rsqrtf(1.f+t*t); s0=t*c0;
                    }
                }
            }
            unsigned msk=__ballot_sync(0xffffffffu,act);
            int cnt=__popc(msk);
            if (!cnt) continue;
            any=1;
            if (act){
                int pos=__popc(msk&((1u<<lane)-1u));
                pqb[pos]=pq; cb[pos]=c0; sb[pos]=s0;
            }
            __syncwarp();
            if (lane<n){
                for (int i=0;i<cnt;i++){
                    int pq2=pqb[i]; int p=pq2>>8, q=pq2&255;
                    float cc=cb[i], ss=sb[i];
                    float akp=A[lane*n+p], akq=A[lane*n+q];
                    A[lane*n+p]=cc*akp-ss*akq; A[lane*n+q]=ss*akp+cc*akq;
                    float vkp=Vv[lane*n+p], vkq=Vv[lane*n+q];
                    Vv[lane*n+p]=cc*vkp-ss*vkq; Vv[lane*n+q]=ss*vkp+cc*vkq;
                }
            }
            __syncwarp();
            if (lane<n){
                for (int i=0;i<cnt;i++){
                    int pq2=pqb[i]; int p=pq2>>8, q=pq2&255;
                    float cc=cb[i], ss=sb[i];
                    float apk=A[p*n+lane], aqk=A[q*n+lane];
                    A[p*n+lane]=cc*apk-ss*aqk; A[q*n+lane]=ss*apk+cc*aqk;
                }
            }
            __syncwarp();
        }
        if (!any) break;
    }
    __syncwarp();
}

__device__ __forceinline__ void eigh4_plain(const float* m, float* a, float* v){
    #pragma unroll
    for (int i=0;i<16;i++){ a[i]=m[i]; v[i]=((i%5)==0)?1.f:0.f; }
    float nrm=0.f;
    #pragma unroll
    for (int i=0;i<16;i++) nrm+=a[i]*a[i];
    float thr=nrm*1e-15f+1e-38f;
    for (int sw=0;sw<10;sw++){
        bool rot=false;
        #pragma unroll
        for (int p=0;p<3;p++){
            #pragma unroll
            for (int q=p+1;q<4;q++){
                float apq=a[p*4+q];
                if (apq*apq>thr){
                    rot=true;
                    float app=a[p*5], aqq=a[q*5];
                    float tau=(aqq-app)/(2.f*apq);
                    float t=copysignf(1.f,tau)/(fabsf(tau)+sqrtf(1.f+tau*tau));
                    float c=rsqrtf(1.f+t*t), s=t*c;
                    #pragma unroll
                    for (int k2=0;k2<4;k2++){
                        float akp=a[k2*4+p], akq=a[k2*4+q];
                        a[k2*4+p]=c*akp-s*akq; a[k2*4+q]=s*akp+c*akq;
                        float vkp=v[k2*4+p], vkq=v[k2*4+q];
                        v[k2*4+p]=c*vkp-s*vkq; v[k2*4+q]=s*vkp+c*vkq;
                    }
                    #pragma unroll
                    for (int k2=0;k2<4;k2++){
                        float apk=a[p*4+k2], aqk=a[q*4+k2];
                        a[p*4+k2]=c*apk-s*aqk; a[q*4+k2]=s*apk+c*aqk;
                    }
                }
            }
        }
        if (!rot) break;
    }
}

__device__ __forceinline__ void eigh4_log(const float* m, float* out){
    float a[16], v[16];
    eigh4_plain(m,a,v);
    float fw[4];
    #pragma unroll
    for (int i=0;i<4;i++) fw[i]=logf(fmaxf(a[i*5],1e-9f));
    #pragma unroll
    for (int i=0;i<16;i++){
        int r2=i/4, c2=i%4;
        float acc=0.f;
        #pragma unroll
        for (int k2=0;k2<4;k2++) acc+=v[r2*4+k2]*fw[k2]*v[c2*4+k2];
        out[i]=acc;
    }
}

__global__ void k_prep(const float* __restrict__ sv0,const float* __restrict__ sv1,
                       const float* __restrict__ sv2,const float* __restrict__ sv3){
    __shared__ float shp[3][1560];
    __shared__ unsigned short ssch[3][231];
    __shared__ float cbs[3][16], sbs[3][16];
    __shared__ int pqs[3][16];
    int warp=threadIdx.x>>5, lane=threadIdx.x&31;
    if (warp==3){
        for (int e=lane;e<625;e+=32){
            int i=e/25, j=e%25;
            float acc=0.f;
            for (int a=0;a<25;a++) acc+=sv3[i*25+a]*(4e-6f*(1.f+a))*sv3[j*25+a];
            g_E11g3[e]=acc;
        }
        return;
    }
    const float* sv=(warp==0?sv0:warp==1?sv1:sv2);
    const int KAP=(warp==0?4:warp==1?9:16);
    const int R=25-KAP;
    float* Wp=shp[warp];
    float* F =Wp+525;
    float* Z =F+441;
    float* Bm=Z+441;
    for (int e=lane;e<KAP*KAP;e+=32){
        int i=e/KAP, j=e%KAP;
        float acc=0.f;
        for (int a=0;a<25;a++) acc+=sv[i*25+a]*(4e-6f*(1.f+a))*sv[j*25+a];
        g_E11[warp*256+i*16+j]=acc;
    }
    __syncwarp();
    int rc=0;
    for (int cand=0; cand<25 && rc<R; cand++){
        float v=(lane==cand)?1.f:0.f;
        for (int pass=0;pass<2;pass++){
            for (int i=0;i<KAP;i++){
                float w=(lane<25)?sv[i*25+lane]:0.f;
                float d=warp_sum(v*w); v-=d*w;
            }
            for (int i=0;i<rc;i++){
                float w=(lane<25)?Wp[i*25+lane]:0.f;
                float d=warp_sum(v*w); v-=d*w;
            }
        }
        float nn=warp_sum(v*v);
        if (nn>1e-4f){
            float inv=rsqrtf(nn);
            if (lane<25) Wp[rc*25+lane]=v*inv;
            rc++;
        }
        __syncwarp();
    }
    for (int e=lane;e<R*R;e+=32){
        int m2=e/R, n2=e%R;
        float acc=0.f;
        for (int a=0;a<25;a++) acc+=Wp[m2*25+a]*(4e-6f*(1.f+a))*Wp[n2*25+a];
        F[e]=acc;
    }
    sched_init_w(ssch[warp],R);
    int m=(R+1)&~1;
    warp_jacobi(F,Z,R,ssch[warp],m-1,m>>1,cbs[warp],sbs[warp],pqs[warp],false);
    if (lane<R) g_mu[warp*21+lane]=F[lane*(R+1)];
    __syncwarp();
    for (int e=lane;e<25*R;e+=32){
        int a=e/R, m2=e%R;
        float acc=0.f;
        for (int t=0;t<R;t++) acc+=Wp[t*25+a]*Z[t*R+m2];
        g_P2[warp*525+a*21+m2]=acc;
    }
    for (int e=lane;e<KAP*R;e+=32){
        int i=e/R, t=e%R;
        float acc=0.f;
        for (int a=0;a<25;a++) acc+=sv[i*25+a]*(4e-6f*(1.f+a))*Wp[t*25+a];
        Bm[e]=acc;
    }
    __syncwarp();
    for (int e=lane;e<KAP*R;e+=32){
        int i=e/R, m2=e%R;
        float acc=0.f;
        for (int t=0;t<R;t++) acc+=Bm[i*R+t]*Z[t*R+m2];
        g_CZ[warp*336+i*21+m2]=acc;
    }
}

__global__ void k_conv1(const float* __restrict__ x, const float* __restrict__ w,
                        const float* __restrict__ cb, const float* __restrict__ bg,
                        const float* __restrict__ bb, const float* __restrict__ bm,
                        const float* __restrict__ bv){
    __shared__ float sw[C1*C1];
    __shared__ float ssc[C1], ssh[C1];
    int tid=threadIdx.x;
    for (int i=tid;i<C1*C1;i+=blockDim.x) sw[i]=w[i];
    if (tid<C1){
        float sc=bg[tid]*rsqrtf(bv[tid]+1e-5f);
        ssc[tid]=sc; ssh[tid]=bb[tid]+(cb[tid]-bm[tid])*sc;
    }
    __syncthreads();
    int b=blockIdx.y; int t=blockIdx.x*blockDim.x+tid;
    if (t>=T0) return;
    float xv[C1];
    #pragma unroll
    for (int h=0;h<C1;h++) xv[h]=x[(b*C1+h)*T0+t];
    #pragma unroll 1
    for (int o=0;o<C1;o++){
        float acc=0.f;
        #pragma unroll
        for (int h=0;h<C1;h++) acc+=xv[h]*sw[o*C1+h];
        g_y1[(b*C1+o)*T0+t]=acc*ssc[o]+ssh[o];
    }
}

__global__ void k_conv2(const float* __restrict__ w2, const float* __restrict__ cb,
                        const float* __restrict__ bg, const float* __restrict__ bb,
                        const float* __restrict__ bm, const float* __restrict__ bv){
    __shared__ float sw[C2*C1*12];
    __shared__ float sy[C1*(TW+12)];
    __shared__ float ssc[C2], ssh[C2];
    int tid=threadIdx.x;
    for (int i=tid;i<C2*C1*12;i+=TW) sw[i]=w2[i];
    if (tid<C2){
        float sc=bg[tid]*rsqrtf(bv[tid]+1e-5f);
        ssc[tid]=sc; ssh[tid]=bb[tid]+(cb[tid]-bm[tid])*sc;
    }
    int b=blockIdx.y; int t0=blockIdx.x*TW;
    for (int i=tid;i<C1*(TW+12);i+=TW){
        int c=i/(TW+12), u=i%(TW+12);
        int tt=t0-6+u;
        sy[i]=(tt>=0 && tt<T0)? g_y1[(b*C1+c)*T0+tt] : 0.f;
    }
    __syncthreads();
    int t=t0+tid;
    if (t>=T1C) return;
    float acc[C2];
    #pragma unroll
    for (int o=0;o<C2;o++) acc[o]=0.f;
    for (int c=0;c<C1;c++){
        float yv[12];
        #pragma unroll
        for (int kk=0;kk<12;kk++) yv[kk]=sy[c*(TW+12)+tid+kk];
        #pragma unroll 1
        for (int o=0;o<C2;o++){
            float a=acc[o];
            #pragma unroll
            for (int kk=0;kk<12;kk++) a+=yv[kk]*sw[(o*C1+c)*12+kk];
            acc[o]=a;
        }
    }
    #pragma unroll 1
    for (int o=0;o<C2;o++) g_sig[(b*C2+o)*T1C+t]=acc[o]*ssc[o]+ssh[o];
}

__global__ void k_cov(){
    __shared__ float s[C2*334];
    __shared__ float cc[325];
    __shared__ float tr_s;
    int u=blockIdx.x, b=u/NEP, e=u%NEP;
    int off=e*334; int L=(e==2)?333:334;
    int tid=threadIdx.x;
    for (int idx=tid; idx<C2*L; idx+=256){
        int c=idx/L, t=idx%L;
        s[c*334+t]=g_sig[(b*C2+c)*T1C+off+t];
    }
    __syncthreads();
    if (tid<C2){
        float acc=0.f;
        for (int t=0;t<L;t++) acc+=s[tid*334+t];
        float mean=acc/(float)L;
        for (int t=0;t<L;t++) s[tid*334+t]-=mean;
    }
    __syncthreads();
    for (int r=tid;r<325;r+=256){
        int i=0, rr=r;
        while (rr>=C2-i){ rr-=C2-i; i++; }
        int j=i+rr;
        float acc=0.f;
        for (int t=0;t<L;t++) acc+=s[i*334+t]*s[j*334+t];
        cc[r]=acc/(float)(L-1);
    }
    __syncthreads();
    if (tid==0){
        float tr=0.f;
        for (int i=0;i<C2;i++) tr+=cc[i*C2 - i*(i-1)/2];
        tr_s=tr;
    }
    __syncthreads();
    float inv=1.f/tr_s;
    float* dst=g_cov+u*625;
    for (int e2=tid;e2<625;e2+=256){
        int i=e2/25, j=e2%25;
        int ii=min(i,j), jj=max(i,j);
        float v=cc[ii*C2 - ii*(ii-1)/2 + (jj-ii)]*inv;
        if (i==j) v+=1e-5f;
        dst[e2]=v;
    }
}

__global__ void k_qk(const float* __restrict__ sk0,const float* __restrict__ sk1,
                     const float* __restrict__ sk2,const float* __restrict__ sk3,
                     const float* __restrict__ sq3){
    __shared__ float scov[4][625];
    __shared__ float sK[4][31*16];
    int warp=threadIdx.x>>5, lane=threadIdx.x&31;
    int u=blockIdx.x*4+warp;
    const float* cov=g_cov+u*625;
    for (int e=lane;e<625;e+=32) scov[warp][e]=cov[e];
    __syncwarp();
    if (lane<31){
        int i=(lane==30)?29:lane;
        int k,pr,pc,gi; patch_info(i,k,pr,pc,gi);
        int kk=k*k;
        const float* W=(lane==30)? sq3 : (gi==0?sk0:gi==1?sk1:gi==2?sk2:sk3);
        float Km[16];
        #pragma unroll
        for (int e=0;e<16;e++) Km[e]=0.f;
        for (int c=0;c<kk;c++){
            int ic=(pr+c/k)*5 + pc + c%k;
            float sa[4]={0.f,0.f,0.f,0.f};
            for (int r=0;r<kk;r++){
                int ir=(pr+r/k)*5 + pc + r%k;
                float xx=scov[warp][ir*25+ic];
                #pragma unroll
                for (int a=0;a<4;a++) sa[a]+=W[r*4+a]*xx;
            }
            #pragma unroll
            for (int a=0;a<4;a++)
                #pragma unroll
                for (int b2=0;b2<4;b2++) Km[a*4+b2]+=sa[a]*W[c*4+b2];
        }
        #pragma unroll
        for (int d=0;d<4;d++) Km[d*5]+=2.5e-5f*(1.f+d);
        float logm[16];
        eigh4_log(Km, logm);
        #pragma unroll
        for (int e=0;e<16;e++) sK[warp][lane*16+e]=logm[e];
    }
    __syncwarp();
    float scval=-1e30f;
    if (lane<30){
        float kn=0.f,cr=0.f,qn=0.f;
        #pragma unroll
        for (int e=0;e<16;e++){
            float a=sK[warp][lane*16+e], q=sK[warp][30*16+e];
            kn+=a*a; cr+=a*q; qn+=q*q;
        }
        float E=fmaxf(kn+qn-2.f*cr,0.f);
        scval=1.f/(1.f+log1pf(E));
    }
    float mx=scval;
    #pragma unroll
    for (int o=16;o;o>>=1) mx=fmaxf(mx,__shfl_xor_sync(0xffffffffu,mx,o));
    float ev=(lane<30)?expf(scval-mx):0.f;
    float sm=warp_sum(ev);
    if (lane<30) g_p[u*30+lane]=ev/sm;
}

template<int KAP>
__device__ void logv_mid(float* A, float* V, int gi, const float* __restrict__ sv,
                         const float* __restrict__ cov, int k, int pr, int pc,
                         const unsigned short* schedS, const unsigned short* sched25,
                         float* cb, float* sb, int* pqb){
    const int lane=threadIdx.x&31;
    const int R=25-KAP;
    const float* E11=g_E11+gi*256;
    const float* mu =g_mu +gi*21;
    const float* P2 =g_P2 +gi*525;
    const float* CZ =g_CZ +gi*336;
    for (int e=lane;e<KAP*KAP;e+=32){
        int r=e/KAP, c=e%KAP;
        int ir=(pr+r/k)*5+pc+r%k;
        int ic=(pr+c/k)*5+pc+c%k;
        A[e]=cov[ir*25+ic]+E11[r*16+c];
    }
    __syncwarp();
    const int m=(KAP+1)&~1;
    warp_jacobi(A,V,KAP,schedS,m-1,m>>1,cb,sb,pqb,false);
    float Yc[KAP];
    float lam=0.f;
    if (lane<KAP){
        #pragma unroll
        for (int t=0;t<KAP;t++) Yc[t]=V[t*KAP+lane];
        lam=A[lane*(KAP+1)];
    }
    __syncwarp();
    for (int e=lane;e<625;e+=32) A[e]=0.f;
    __syncwarp();
    if (lane<KAP){
        A[lane*26]=lam;
        #pragma unroll 1
        for (int mm2=0;mm2<R;mm2++){
            float g=0.f;
            #pragma unroll
            for (int t=0;t<KAP;t++) g+=Yc[t]*CZ[t*21+mm2];
            A[lane*25+(KAP+mm2)]=g;
            A[(KAP+mm2)*25+lane]=g;
        }
    } else if (lane<25){
        A[lane*26]=mu[lane-KAP];
    }
    for (int e=lane;e<25*R;e+=32){
        int a=e/R, mm2=e%R;
        V[a*25+KAP+mm2]=P2[a*21+mm2];
    }
    __syncwarp();
    if (lane<KAP){
        #pragma unroll 1
        for (int a=0;a<25;a++){
            float val=0.f;
            #pragma unroll
            for (int i2=0;i2<KAP;i2++) val+=sv[i2*25+a]*Yc[i2];
            V[a*25+lane]=val;
        }
    }
    __syncwarp();
    warp_jacobi(A,V,25,sched25,25,13,cb,sb,pqb,true);
}

__global__ void k_logV(const float* __restrict__ sv0,const float* __restrict__ sv1,
                       const float* __restrict__ sv2,const float* __restrict__ sv3){
    __shared__ float sh[WJ][1250];
    __shared__ float scb[WJ][16], ssb[WJ][16];
    __shared__ int spq[WJ][16];
    __shared__ float sd[WJ][25];
    __shared__ unsigned short sched25[325];
    __shared__ unsigned short sched9[45];
    __shared__ unsigned short sched16[120];
    __shared__ unsigned short tri25[325];
    sched_init(sched25,25);
    sched_init(sched9,9);
    sched_init(sched16,16);
    tri_init(tri25,25);
    int warp=threadIdx.x>>5, lane=threadIdx.x&31;
    int gw=blockIdx.x*WJ+warp;
    if (gw>=NU*MM) return;
    int u=gw/MM, i=gw%MM;
    float* A=sh[warp]; float* V=A+625;
    int k,pr,pc,gi; patch_info(i,k,pr,pc,gi);
    const float* cov=g_cov+u*625;
    if (gi==0){
        float sm4[16], av[16], vv[16];
        #pragma unroll
        for (int e=0;e<16;e++){
            int r=e>>2, c=e&3;
            int ir=(pr+(r>>1))*5+pc+(r&1);
            int ic=(pr+(c>>1))*5+pc+(c&1);
            sm4[e]=cov[ir*25+ic]+g_E11[r*16+c];
        }
        eigh4_plain(sm4,av,vv);
        for (int e=lane;e<625;e+=32){
            int a=e/25, b=e%25;
            float val=0.f;
            if (a==b) val=(a<4)? av[a*5] : g_mu[a-4];
            else if (a<4 && b>=4){
                #pragma unroll
                for (int t=0;t<4;t++) val+=vv[t*4+a]*g_CZ[t*21+(b-4)];
            } else if (b<4 && a>=4){
                #pragma unroll
                for (int t=0;t<4;t++) val+=vv[t*4+b]*g_CZ[t*21+(a-4)];
            }
            A[e]=val;
        }
        for (int e=lane;e<625;e+=32){
            int a=e/25, j=e%25;
            float val;
            if (j<4){
                val=0.f;
                #pragma unroll
                for (int i2=0;i2<4;i2++) val+=sv0[i2*25+a]*vv[i2*4+j];
            } else val=g_P2[a*21+(j-4)];
            V[e]=val;
        }
        __syncwarp();
        warp_jacobi(A,V,25,sched25,25,13,scb[warp],ssb[warp],spq[warp],true);
    } else if (gi==1){
        logv_mid<9>(A,V,1,sv1,cov,k,pr,pc,sched9,sched25,scb[warp],ssb[warp],spq[warp]);
    } else if (gi==2){
        logv_mid<16>(A,V,2,sv2,cov,k,pr,pc,sched16,sched25,scb[warp],ssb[warp],spq[warp]);
    } else {
        for (int e=lane;e<625;e+=32) A[e]=cov[e]+g_E11g3[e];
        for (int e=lane;e<625;e+=32){
            int a=e/25, j=e%25;
            V[e]=sv3[j*25+a];
        }
        __syncwarp();
        warp_jacobi(A,V,25,sched25,25,13,scb[warp],ssb[warp],spq[warp],true);
    }
    if (lane<25) sd[warp][lane]=logf(fmaxf(A[lane*26],1e-9f));
    __syncwarp();
    for (int e=lane;e<625;e+=32) A[e]=V[e]*sd[warp][e%25];
    __syncwarp();
    float* out=g_V+(size_t)gw*325;
    for (int r=lane;r<325;r+=32){
        int ij=tri25[r]; int a=ij>>8, b=ij&255;
        float acc=0.f;
        #pragma unroll 5
        for (int kx=0;kx<25;kx++) acc+=A[a*25+kx]*V[b*25+kx];
        out[r]=acc;
    }
}

__global__ void k_att1(){
    __shared__ float sh[WJ][1250];
    __shared__ float scb[WJ][16], ssb[WJ][16];
    __shared__ int spq[WJ][16];
    __shared__ float sd[WJ][25];
    __shared__ unsigned short sched[325];
    __shared__ unsigned short tri25[325];
    __shared__ float pp[WJ][30];
    sched_init(sched,25);
    tri_init(tri25,25);
    int warp=threadIdx.x>>5, lane=threadIdx.x&31;
    int u=blockIdx.x*WJ+warp;
    if (u>=NU) return;
    float* A=sh[warp]; float* V=A+625;
    if (lane<30) pp[warp][lane]=g_p[u*30+lane];
    __syncwarp();
    const float* Vb=g_V+(size_t)u*30*325;
    for (int r=lane;r<325;r+=32){
        float acc=0.f;
        #pragma unroll 5
        for (int i=0;i<30;i++) acc+=pp[warp][i]*Vb[(size_t)i*325+r];
        int ij=tri25[r]; int a=ij>>8, b=ij&255;
        A[a*25+b]=acc; A[b*25+a]=acc;
    }
    __syncwarp();
    warp_jacobi(A,V,25,sched,25,13,scb[warp],ssb[warp],spq[warp],false);
    if (lane<25) sd[warp][lane]=fmaxf(expf(A[lane*26]),1e-4f);
    __syncwarp();
    for (int e=lane;e<625;e+=32) A[e]=V[e]*sd[warp][e%25];
    __syncwarp();
    float* dst=g_xm+u*625;
    for (int r=lane;r<325;r+=32){
        int ij=tri25[r]; int a=ij>>8, b=ij&255;
        float acc=0.f;
        #pragma unroll 5
        for (int kx=0;kx<25;kx++) acc+=A[a*25+kx]*V[b*25+kx];
        dst[a*25+b]=acc; dst[b*25+a]=acc;
    }
}

__global__ void k_s2log(const float* __restrict__ mq,const float* __restrict__ mk,
                        const float* __restrict__ mv){
    __shared__ float sh[WJ][1250];
    __shared__ float scb[WJ][16], ssb[WJ][16];
    __shared__ int spq[WJ][16];
    __shared__ float sd[WJ][18];
    __shared__ unsigned short sched[153];
    __shared__ unsigned short tri18[171];
    sched_init(sched,18);
    tri_init(tri18,18);
    int warp=threadIdx.x>>5, lane=threadIdx.x&31;
    int id=blockIdx.x*WJ+warp;
    if (id>=BB*9) return;
    int b=id/9, rem=id%9, t=rem/3, c=rem%3;
    float* A=sh[warp]; float* V=A+625;
    const float* W=(c==0?mq:(c==1?mk:mv));
    const float* X=g_xm+(b*3+t)*625;
    for (int e=lane;e<450;e+=32){
        int r=e/18, a=e%18;
        float acc=0.f;
        for (int cc=0;cc<25;cc++) acc+=X[r*25+cc]*W[cc*18+a];
        V[e]=acc;
    }
    __syncwarp();
    for (int e=lane;e<324;e+=32){
        int a=e/18, bb=e%18;
        float acc=0.f;
        for (int r=0;r<25;r++) acc+=W[r*18+a]*V[r*18+bb];
        A[e]=acc;
    }
    __syncwarp();
    warp_jacobi(A,V,18,sched,17,9,scb[warp],ssb[warp],spq[warp],false);
    if (lane<18) sd[warp][lane]=logf(fmaxf(A[lane*19],1e-9f));
    __syncwarp();
    for (int e=lane;e<324;e+=32) A[e]=V[e]*sd[warp][e%18];
    __syncwarp();
    float* dst=(c==0?g_logQ2:(c==1?g_logK2:g_logV2))+(b*3+t)*324;
    for (int r=lane;r<171;r+=32){
        int ij=tri18[r]; int a=ij>>8, bb=ij&255;
        float acc=0.f;
        #pragma unroll 6
        for (int kx=0;kx<18;kx++) acc+=A[a*18+kx]*V[bb*18+kx];
        dst[a*18+bb]=acc; dst[bb*18+a]=acc;
    }
}

__global__ void k_s2att(){
    __shared__ float sh[WJ][1250];
    __shared__ float scb[WJ][16], ssb[WJ][16];
    __shared__ int spq[WJ][16];
    __shared__ float sd[WJ][18];
    __shared__ unsigned short sched[153];
    __shared__ unsigned short tri18[171];
    sched_init(sched,18);
    tri_init(tri18,18);
    int warp=threadIdx.x>>5, lane=threadIdx.x&31;
    int id=blockIdx.x*WJ+warp;
    if (id>=BB*3) return;
    int b=id/3, j=id%3;
    float* A=sh[warp]; float* V=A+625;
    const float* lQ=g_logQ2+(b*3+j)*324;
    float qn=0.f;
    for (int e=lane;e<324;e+=32){ float v=lQ[e]; qn+=v*v; }
    qn=warp_sum(qn);
    float p3[3];
    #pragma unroll
    for (int i=0;i<3;i++){
        const float* lK=g_logK2+(b*3+i)*324;
        float kn=0.f, cr=0.f;
        for (int e=lane;e<324;e+=32){ float a=lK[e], q=lQ[e]; kn+=a*a; cr+=a*q; }
        kn=warp_sum(kn); cr=warp_sum(cr);
        float E=fmaxf(kn+qn-2.f*cr,0.f);
        p3[i]=1.f/(1.f+log1pf(E));
    }
    float mx=fmaxf(p3[0],fmaxf(p3[1],p3[2]));
    float sm=0.f;
    #pragma unroll
    for (int i=0;i<3;i++){ p3[i]=expf(p3[i]-mx); sm+=p3[i]; }
    #pragma unroll
    for (int i=0;i<3;i++) p3[i]/=sm;
    for (int e=lane;e<324;e+=32){
        float acc=0.f;
        #pragma unroll
        for (int i=0;i<3;i++) acc+=p3[i]*g_logV2[(b*3+i)*324+e];
        A[e]=acc;
    }
    __syncwarp();
    warp_jacobi(A,V,18,sched,17,9,scb[warp],ssb[warp],spq[warp],false);
    if (lane<18) sd[warp][lane]=fmaxf(A[lane*19],-9.210340371976184f);
    __syncwarp();
    for (int e=lane;e<324;e+=32) A[e]=V[e]*sd[warp][e%18];
    __syncwarp();
    for (int r=lane;r<171;r+=32){
        int ij=tri18[r]; int ii=ij>>8, jj=ij&255;
        float acc=0.f;
        #pragma unroll 6
        for (int kx=0;kx<18;kx++) acc+=A[ii*18+kx]*V[jj*18+kx];
        float coef=(ii==jj)?1.f:1.41421356237309515f;
        g_feat[b*513 + j*171 + r]=acc*coef;
    }
}

__global__ void k_head(const float* __restrict__ lw, const float* __restrict__ lb,
                       float* __restrict__ out){
    int b=blockIdx.x; int o=threadIdx.x>>5; int lane=threadIdx.x&31;
    if (o>=4) return;
    float acc=0.f;
    for (int r=lane;r<513;r+=32) acc+=g_feat[b*513+r]*lw[o*513+r];
    acc=warp_sum(acc);
    if (lane==0) out[b*4+o]=acc+lb[o];
}

extern "C" void kernel_launch(void* const* d_in, const int* in_sizes, int n_in,
                              void* d_out, int out_size){
    const float* x   =(const float*)d_in[0];
    const float* c1w =(const float*)d_in[1];
    const float* c1b =(const float*)d_in[2];
    const float* bn1g=(const float*)d_in[3];
    const float* bn1b=(const float*)d_in[4];
    const float* bn1m=(const float*)d_in[5];
    const float* bn1v=(const float*)d_in[6];
    const float* c2w =(const float*)d_in[7];
    const float* c2b =(const float*)d_in[8];
    const float* bn2g=(const float*)d_in[9];
    const float* bn2b=(const float*)d_in[10];
    const float* bn2m=(const float*)d_in[11];
    const float* bn2v=(const float*)d_in[12];
    bool inter = (in_sizes[14]==16);
    const float *sk[4], *sv[4], *sq3p;
    if (inter){
        sq3p=(const float*)d_in[13+3*3];
        for (int g=0; g<4; g++){
            sk[g]=(const float*)d_in[14+3*g];
            sv[g]=(const float*)d_in[15+3*g];
        }
    } else {
        sq3p=(const float*)d_in[16];
        for (int g=0; g<4; g++){
            sk[g]=(const float*)d_in[17+g];
            sv[g]=(const float*)d_in[21+g];
        }
    }
    const float* mq=(const float*)d_in[25];
    const float* mk=(const float*)d_in[26];
    const float* mv=(const float*)d_in[27];
    const float* lw=(const float*)d_in[28];
    const float* lb=(const float*)d_in[29];

    k_prep <<<1,128>>>(sv[0],sv[1],sv[2],sv[3]);
    k_conv1<<<dim3(8,BB),128>>>(x,c1w,c1b,bn1g,bn1b,bn1m,bn1v);
    k_conv2<<<dim3(8,BB),128>>>(c2w,c2b,bn2g,bn2b,bn2m,bn2v);
    k_cov  <<<NU,256>>>();
    k_qk   <<<NU/4,128>>>(sk[0],sk[1],sk[2],sk[3],sq3p);
    k_logV <<<(NU*MM+WJ-1)/WJ,WJ*32>>>(sv[0],sv[1],sv[2],sv[3]);
    k_att1 <<<(NU+WJ-1)/WJ,WJ*32>>>();
    k_s2log<<<(BB*9+WJ-1)/WJ,WJ*32>>>(mq,mk,mv);
    k_s2att<<<(BB*3+WJ-1)/WJ,WJ*32>>>();
    k_head <<<BB,128>>>(lw,lb,(float*)d_out);
}

// round 13
// speedup vs baseline: 1.4464x; 1.0289x over previous
#include <cuda_runtime.h>
#include <cuda_bf16.h>

#define BB   256
#define T0   1000
#define T1C  1001
#define C1   22
#define C2   25
#define NEP  3
#define NU   (BB*NEP)
#define MM   30
#define TW   128
#define WJ   8

__device__ float g_y1  [BB*C1*T0];
__device__ float g_sig [BB*C2*T1C];
__device__ float g_cov [NU*625];
__device__ float g_V   [NU*MM*325];
__device__ float g_p   [NU*MM];
__device__ float g_xm  [NU*625];
__device__ float g_logQ2[BB*3*324];
__device__ float g_logK2[BB*3*324];
__device__ float g_logV2[BB*3*324];
__device__ float g_feat [BB*513];
__device__ float g_P2 [3*525];
__device__ float g_CZ [3*336];
__device__ float g_E11[3*256];
__device__ float g_mu [3*21];
__device__ float g_E11g3[625];

__device__ __forceinline__ float warp_sum(float v){
    #pragma unroll
    for (int o=16;o;o>>=1) v += __shfl_xor_sync(0xffffffffu, v, o);
    return v;
}

__device__ __forceinline__ void patch_info(int i, int&k, int&pr, int&pc, int&gi){
    if (i<16){ gi=0;k=2;pr=i/4;pc=i%4; }
    else if (i<25){ gi=1;k=3;int p=i-16;pr=p/3;pc=p%3; }
    else if (i<29){ gi=2;k=4;int p=i-25;pr=p/2;pc=p%2; }
    else { gi=3;k=5;pr=0;pc=0; }
}

__device__ void sched_init(unsigned short* sched, int n){
    int m=(n+1)&~1, P=m>>1, R=m-1;
    for (int idx=threadIdx.x; idx<R*P; idx+=blockDim.x){
        int r=idx/P, i=idx%P;
        int j=m-1-i;
        int a=(i==0)?0:(1+(r+i-1)%(m-1));
        int b=1+(r+j-1)%(m-1);
        int p=min(a,b), q=max(a,b);
        sched[idx]=(q<n)? (unsigned short)((p<<8)|q) : (unsigned short)0xFFFF;
    }
    __syncthreads();
}
__device__ void sched_init_w(unsigned short* sched, int n){
    int lane=threadIdx.x&31;
    int m=(n+1)&~1, P=m>>1, R=m-1;
    for (int idx=lane; idx<R*P; idx+=32){
        int r=idx/P, i=idx%P;
        int j=m-1-i;
        int a=(i==0)?0:(1+(r+i-1)%(m-1));
        int b=1+(r+j-1)%(m-1);
        int p=min(a,b), q=max(a,b);
        sched[idx]=(q<n)? (unsigned short)((p<<8)|q) : (unsigned short)0xFFFF;
    }
    __syncwarp();
}
__device__ void tri_init(unsigned short* tri, int n){
    for (int r=threadIdx.x; r<n*(n+1)/2; r+=blockDim.x){
        int i=0, rr=r;
        while (rr>=n-i){ rr-=n-i; i++; }
        tri[r]=(unsigned short)((i<<8)|(i+rr));
    }
    __syncthreads();
}

// Tournament-batched Jacobi (threshold relaxed to 1e-13).
__device__ void warp_jacobi(float* A, float* Vv, int n, const unsigned short* sched,
                            int R, int P, float* cb, float* sb, int* pqb, bool preV){
    int lane=threadIdx.x&31;
    if (!preV) for (int e=lane;e<n*n;e+=32) Vv[e]=((e%(n+1))==0)?1.f:0.f;
    float nrm=0.f;
    for (int e=lane;e<n*n;e+=32) nrm+=A[e]*A[e];
    nrm=warp_sum(nrm);
    float thr=nrm*1e-13f+1e-38f;
    __syncwarp();
    for (int sweep=0;sweep<24;sweep++){
        int any=0;
        for (int r=0;r<R;r++){
            bool act=false; int pq=0; float c0=1.f,s0=0.f;
            if (lane<P){
                pq=sched[r*P+lane];
                if (pq!=0xFFFF){
                    int p=pq>>8, q=pq&255;
                    float apq=A[p*n+q];
                    if (apq*apq>thr){
                        act=true;
                        float app=A[p*n+p], aqq=A[q*n+q];
                        float tau=(aqq-app)/(2.f*apq);
                        float t=copysignf(1.f,tau)/(fabsf(tau)+sqrtf(1.f+tau*tau));
                        c0=rsqrtf(1.f+t*t); s0=t*c0;
                    }
                }
            }
            unsigned msk=__ballot_sync(0xffffffffu,act);
            int cnt=__popc(msk);
            if (!cnt) continue;
            any=1;
            if (act){
                int pos=__popc(msk&((1u<<lane)-1u));
                pqb[pos]=pq; cb[pos]=c0; sb[pos]=s0;
            }
            __syncwarp();
            if (lane<n){
                for (int i=0;i<cnt;i++){
                    int pq2=pqb[i]; int p=pq2>>8, q=pq2&255;
                    float cc=cb[i], ss=sb[i];
                    float akp=A[lane*n+p], akq=A[lane*n+q];
                    A[lane*n+p]=cc*akp-ss*akq; A[lane*n+q]=ss*akp+cc*akq;
                    float vkp=Vv[lane*n+p], vkq=Vv[lane*n+q];
                    Vv[lane*n+p]=cc*vkp-ss*vkq; Vv[lane*n+q]=ss*vkp+cc*vkq;
                }
            }
            __syncwarp();
            if (lane<n){
                for (int i=0;i<cnt;i++){
                    int pq2=pqb[i]; int p=pq2>>8, q=pq2&255;
                    float cc=cb[i], ss=sb[i];
                    float apk=A[p*n+lane], aqk=A[q*n+lane];
                    A[p*n+lane]=cc*apk-ss*aqk; A[q*n+lane]=ss*apk+cc*aqk;
                }
            }
            __syncwarp();
        }
        if (!any) break;
    }
    __syncwarp();
}

__device__ __forceinline__ void eigh4_plain(const float* m, float* a, float* v){
    #pragma unroll
    for (int i=0;i<16;i++){ a[i]=m[i]; v[i]=((i%5)==0)?1.f:0.f; }
    float nrm=0.f;
    #pragma unroll
    for (int i=0;i<16;i++) nrm+=a[i]*a[i];
    float thr=nrm*1e-15f+1e-38f;
    for (int sw=0;sw<10;sw++){
        bool rot=false;
        #pragma unroll
        for (int p=0;p<3;p++){
            #pragma unroll
            for (int q=p+1;q<4;q++){
                float apq=a[p*4+q];
                if (apq*apq>thr){
                    rot=true;
                    float app=a[p*5], aqq=a[q*5];
                    float tau=(aqq-app)/(2.f*apq);
                    float t=copysignf(1.f,tau)/(fabsf(tau)+sqrtf(1.f+tau*tau));
                    float c=rsqrtf(1.f+t*t), s=t*c;
                    #pragma unroll
                    for (int k2=0;k2<4;k2++){
                        float akp=a[k2*4+p], akq=a[k2*4+q];
                        a[k2*4+p]=c*akp-s*akq; a[k2*4+q]=s*akp+c*akq;
                        float vkp=v[k2*4+p], vkq=v[k2*4+q];
                        v[k2*4+p]=c*vkp-s*vkq; v[k2*4+q]=s*vkp+c*vkq;
                    }
                    #pragma unroll
                    for (int k2=0;k2<4;k2++){
                        float apk=a[p*4+k2], aqk=a[q*4+k2];
                        a[p*4+k2]=c*apk-s*aqk; a[q*4+k2]=s*apk+c*aqk;
                    }
                }
            }
        }
        if (!rot) break;
    }
}

__device__ __forceinline__ void eigh4_log(const float* m, float* out){
    float a[16], v[16];
    eigh4_plain(m,a,v);
    float fw[4];
    #pragma unroll
    for (int i=0;i<4;i++) fw[i]=logf(fmaxf(a[i*5],1e-9f));
    #pragma unroll
    for (int i=0;i<16;i++){
        int r2=i/4, c2=i%4;
        float acc=0.f;
        #pragma unroll
        for (int k2=0;k2<4;k2++) acc+=v[r2*4+k2]*fw[k2]*v[c2*4+k2];
        out[i]=acc;
    }
}

__global__ void k_prep(const float* __restrict__ sv0,const float* __restrict__ sv1,
                       const float* __restrict__ sv2,const float* __restrict__ sv3){
    __shared__ float shp[3][1560];
    __shared__ unsigned short ssch[3][231];
    __shared__ float cbs[3][16], sbs[3][16];
    __shared__ int pqs[3][16];
    int warp=threadIdx.x>>5, lane=threadIdx.x&31;
    if (warp==3){
        for (int e=lane;e<625;e+=32){
            int i=e/25, j=e%25;
            float acc=0.f;
            for (int a=0;a<25;a++) acc+=sv3[i*25+a]*(4e-6f*(1.f+a))*sv3[j*25+a];
            g_E11g3[e]=acc;
        }
        return;
    }
    const float* sv=(warp==0?sv0:warp==1?sv1:sv2);
    const int KAP=(warp==0?4:warp==1?9:16);
    const int R=25-KAP;
    float* Wp=shp[warp];
    float* F =Wp+525;
    float* Z =F+441;
    float* Bm=Z+441;
    for (int e=lane;e<KAP*KAP;e+=32){
        int i=e/KAP, j=e%KAP;
        float acc=0.f;
        for (int a=0;a<25;a++) acc+=sv[i*25+a]*(4e-6f*(1.f+a))*sv[j*25+a];
        g_E11[warp*256+i*16+j]=acc;
    }
    __syncwarp();
    int rc=0;
    for (int cand=0; cand<25 && rc<R; cand++){
        float v=(lane==cand)?1.f:0.f;
        for (int pass=0;pass<2;pass++){
            for (int i=0;i<KAP;i++){
                float w=(lane<25)?sv[i*25+lane]:0.f;
                float d=warp_sum(v*w); v-=d*w;
            }
            for (int i=0;i<rc;i++){
                float w=(lane<25)?Wp[i*25+lane]:0.f;
                float d=warp_sum(v*w); v-=d*w;
            }
        }
        float nn=warp_sum(v*v);
        if (nn>1e-4f){
            float inv=rsqrtf(nn);
            if (lane<25) Wp[rc*25+lane]=v*inv;
            rc++;
        }
        __syncwarp();
    }
    for (int e=lane;e<R*R;e+=32){
        int m2=e/R, n2=e%R;
        float acc=0.f;
        for (int a=0;a<25;a++) acc+=Wp[m2*25+a]*(4e-6f*(1.f+a))*Wp[n2*25+a];
        F[e]=acc;
    }
    sched_init_w(ssch[warp],R);
    int m=(R+1)&~1;
    warp_jacobi(F,Z,R,ssch[warp],m-1,m>>1,cbs[warp],sbs[warp],pqs[warp],false);
    if (lane<R) g_mu[warp*21+lane]=F[lane*(R+1)];
    __syncwarp();
    for (int e=lane;e<25*R;e+=32){
        int a=e/R, m2=e%R;
        float acc=0.f;
        for (int t=0;t<R;t++) acc+=Wp[t*25+a]*Z[t*R+m2];
        g_P2[warp*525+a*21+m2]=acc;
    }
    for (int e=lane;e<KAP*R;e+=32){
        int i=e/R, t=e%R;
        float acc=0.f;
        for (int a=0;a<25;a++) acc+=sv[i*25+a]*(4e-6f*(1.f+a))*Wp[t*25+a];
        Bm[e]=acc;
    }
    __syncwarp();
    for (int e=lane;e<KAP*R;e+=32){
        int i=e/R, m2=e%R;
        float acc=0.f;
        for (int t=0;t<R;t++) acc+=Bm[i*R+t]*Z[t*R+m2];
        g_CZ[warp*336+i*21+m2]=acc;
    }
}

__global__ void k_conv1(const float* __restrict__ x, const float* __restrict__ w,
                        const float* __restrict__ cb, const float* __restrict__ bg,
                        const float* __restrict__ bb, const float* __restrict__ bm,
                        const float* __restrict__ bv){
    __shared__ float sw[C1*C1];
    __shared__ float ssc[C1], ssh[C1];
    int tid=threadIdx.x;
    for (int i=tid;i<C1*C1;i+=blockDim.x) sw[i]=w[i];
    if (tid<C1){
        float sc=bg[tid]*rsqrtf(bv[tid]+1e-5f);
        ssc[tid]=sc; ssh[tid]=bb[tid]+(cb[tid]-bm[tid])*sc;
    }
    __syncthreads();
    int b=blockIdx.y; int t=blockIdx.x*blockDim.x+tid;
    if (t>=T0) return;
    float xv[C1];
    #pragma unroll
    for (int h=0;h<C1;h++) xv[h]=x[(b*C1+h)*T0+t];
    #pragma unroll 1
    for (int o=0;o<C1;o++){
        float acc=0.f;
        #pragma unroll
        for (int h=0;h<C1;h++) acc+=xv[h]*sw[o*C1+h];
        g_y1[(b*C1+o)*T0+t]=acc*ssc[o]+ssh[o];
    }
}

__global__ void k_conv2(const float* __restrict__ w2, const float* __restrict__ cb,
                        const float* __restrict__ bg, const float* __restrict__ bb,
                        const float* __restrict__ bm, const float* __restrict__ bv){
    __shared__ float sw[C2*C1*12];
    __shared__ float sy[C1*(TW+12)];
    __shared__ float ssc[C2], ssh[C2];
    int tid=threadIdx.x;
    for (int i=tid;i<C2*C1*12;i+=TW) sw[i]=w2[i];
    if (tid<C2){
        float sc=bg[tid]*rsqrtf(bv[tid]+1e-5f);
        ssc[tid]=sc; ssh[tid]=bb[tid]+(cb[tid]-bm[tid])*sc;
    }
    int b=blockIdx.y; int t0=blockIdx.x*TW;
    for (int i=tid;i<C1*(TW+12);i+=TW){
        int c=i/(TW+12), u=i%(TW+12);
        int tt=t0-6+u;
        sy[i]=(tt>=0 && tt<T0)? g_y1[(b*C1+c)*T0+tt] : 0.f;
    }
    __syncthreads();
    int t=t0+tid;
    if (t>=T1C) return;
    float acc[C2];
    #pragma unroll
    for (int o=0;o<C2;o++) acc[o]=0.f;
    for (int c=0;c<C1;c++){
        float yv[12];
        #pragma unroll
        for (int kk=0;kk<12;kk++) yv[kk]=sy[c*(TW+12)+tid+kk];
        #pragma unroll 1
        for (int o=0;o<C2;o++){
            float a=acc[o];
            #pragma unroll
            for (int kk=0;kk<12;kk++) a+=yv[kk]*sw[(o*C1+c)*12+kk];
            acc[o]=a;
        }
    }
    #pragma unroll 1
    for (int o=0;o<C2;o++) g_sig[(b*C2+o)*T1C+t]=acc[o]*ssc[o]+ssh[o];
}

__global__ void k_cov(){
    __shared__ float s[C2*334];
    __shared__ float cc[325];
    __shared__ float tr_s;
    int u=blockIdx.x, b=u/NEP, e=u%NEP;
    int off=e*334; int L=(e==2)?333:334;
    int tid=threadIdx.x;
    for (int idx=tid; idx<C2*L; idx+=256){
        int c=idx/L, t=idx%L;
        s[c*334+t]=g_sig[(b*C2+c)*T1C+off+t];
    }
    __syncthreads();
    if (tid<C2){
        float acc=0.f;
        for (int t=0;t<L;t++) acc+=s[tid*334+t];
        float mean=acc/(float)L;
        for (int t=0;t<L;t++) s[tid*334+t]-=mean;
    }
    __syncthreads();
    for (int r=tid;r<325;r+=256){
        int i=0, rr=r;
        while (rr>=C2-i){ rr-=C2-i; i++; }
        int j=i+rr;
        float acc=0.f;
        for (int t=0;t<L;t++) acc+=s[i*334+t]*s[j*334+t];
        cc[r]=acc/(float)(L-1);
    }
    __syncthreads();
    if (tid==0){
        float tr=0.f;
        for (int i=0;i<C2;i++) tr+=cc[i*C2 - i*(i-1)/2];
        tr_s=tr;
    }
    __syncthreads();
    float inv=1.f/tr_s;
    float* dst=g_cov+u*625;
    for (int e2=tid;e2<625;e2+=256){
        int i=e2/25, j=e2%25;
        int ii=min(i,j), jj=max(i,j);
        float v=cc[ii*C2 - ii*(ii-1)/2 + (jj-ii)]*inv;
        if (i==j) v+=1e-5f;
        dst[e2]=v;
    }
}

__global__ void k_qk(const float* __restrict__ sk0,const float* __restrict__ sk1,
                     const float* __restrict__ sk2,const float* __restrict__ sk3,
                     const float* __restrict__ sq3){
    __shared__ float scov[4][625];
    __shared__ float sK[4][31*16];
    int warp=threadIdx.x>>5, lane=threadIdx.x&31;
    int u=blockIdx.x*4+warp;
    const float* cov=g_cov+u*625;
    for (int e=lane;e<625;e+=32) scov[warp][e]=cov[e];
    __syncwarp();
    if (lane<31){
        int i=(lane==30)?29:lane;
        int k,pr,pc,gi; patch_info(i,k,pr,pc,gi);
        int kk=k*k;
        const float* W=(lane==30)? sq3 : (gi==0?sk0:gi==1?sk1:gi==2?sk2:sk3);
        float Km[16];
        #pragma unroll
        for (int e=0;e<16;e++) Km[e]=0.f;
        for (int c=0;c<kk;c++){
            int ic=(pr+c/k)*5 + pc + c%k;
            float sa[4]={0.f,0.f,0.f,0.f};
            for (int r=0;r<kk;r++){
                int ir=(pr+r/k)*5 + pc + r%k;
                float xx=scov[warp][ir*25+ic];
                #pragma unroll
                for (int a=0;a<4;a++) sa[a]+=W[r*4+a]*xx;
            }
            #pragma unroll
            for (int a=0;a<4;a++)
                #pragma unroll
                for (int b2=0;b2<4;b2++) Km[a*4+b2]+=sa[a]*W[c*4+b2];
        }
        #pragma unroll
        for (int d=0;d<4;d++) Km[d*5]+=2.5e-5f*(1.f+d);
        float logm[16];
        eigh4_log(Km, logm);
        #pragma unroll
        for (int e=0;e<16;e++) sK[warp][lane*16+e]=logm[e];
    }
    __syncwarp();
    float scval=-1e30f;
    if (lane<30){
        float kn=0.f,cr=0.f,qn=0.f;
        #pragma unroll
        for (int e=0;e<16;e++){
            float a=sK[warp][lane*16+e], q=sK[warp][30*16+e];
            kn+=a*a; cr+=a*q; qn+=q*q;
        }
        float E=fmaxf(kn+qn-2.f*cr,0.f);
        scval=1.f/(1.f+log1pf(E));
    }
    float mx=scval;
    #pragma unroll
    for (int o=16;o;o>>=1) mx=fmaxf(mx,__shfl_xor_sync(0xffffffffu,mx,o));
    float ev=(lane<30)?expf(scval-mx):0.f;
    float sm=warp_sum(ev);
    if (lane<30) g_p[u*30+lane]=ev/sm;
}

template<int KAP>
__device__ void logv_mid(float* A, float* V, int gi, const float* __restrict__ sv,
                         const float* __restrict__ cov, int k, int pr, int pc,
                         const unsigned short* schedS, const unsigned short* sched25,
                         float* cb, float* sb, int* pqb){
    const int lane=threadIdx.x&31;
    const int R=25-KAP;
    const float* E11=g_E11+gi*256;
    const float* mu =g_mu +gi*21;
    const float* P2 =g_P2 +gi*525;
    const float* CZ =g_CZ +gi*336;
    for (int e=lane;e<KAP*KAP;e+=32){
        int r=e/KAP, c=e%KAP;
        int ir=(pr+r/k)*5+pc+r%k;
        int ic=(pr+c/k)*5+pc+c%k;
        A[e]=cov[ir*25+ic]+E11[r*16+c];
    }
    __syncwarp();
    const int m=(KAP+1)&~1;
    warp_jacobi(A,V,KAP,schedS,m-1,m>>1,cb,sb,pqb,false);
    float Yc[KAP];
    float lam=0.f;
    if (lane<KAP){
        #pragma unroll
        for (int t=0;t<KAP;t++) Yc[t]=V[t*KAP+lane];
        lam=A[lane*(KAP+1)];
    }
    __syncwarp();
    for (int e=lane;e<625;e+=32) A[e]=0.f;
    __syncwarp();
    if (lane<KAP){
        A[lane*26]=lam;
        #pragma unroll 1
        for (int mm2=0;mm2<R;mm2++){
            float g=0.f;
            #pragma unroll
            for (int t=0;t<KAP;t++) g+=Yc[t]*CZ[t*21+mm2];
            A[lane*25+(KAP+mm2)]=g;
            A[(KAP+mm2)*25+lane]=g;
        }
    } else if (lane<25){
        A[lane*26]=mu[lane-KAP];
    }
    for (int e=lane;e<25*R;e+=32){
        int a=e/R, mm2=e%R;
        V[a*25+KAP+mm2]=P2[a*21+mm2];
    }
    __syncwarp();
    if (lane<KAP){
        #pragma unroll 1
        for (int a=0;a<25;a++){
            float val=0.f;
            #pragma unroll
            for (int i2=0;i2<KAP;i2++) val+=sv[i2*25+a]*Yc[i2];
            V[a*25+lane]=val;
        }
    }
    __syncwarp();
    warp_jacobi(A,V,25,sched25,25,13,cb,sb,pqb,true);
}

__global__ void k_logV(const float* __restrict__ sv0,const float* __restrict__ sv1,
                       const float* __restrict__ sv2,const float* __restrict__ sv3){
    __shared__ float sh[WJ][1250];
    __shared__ float scb[WJ][16], ssb[WJ][16];
    __shared__ int spq[WJ][16];
    __shared__ float sd[WJ][25];
    __shared__ unsigned short sched25[325];
    __shared__ unsigned short sched9[45];
    __shared__ unsigned short sched16[120];
    __shared__ unsigned short tri25[325];
    sched_init(sched25,25);
    sched_init(sched9,9);
    sched_init(sched16,16);
    tri_init(tri25,25);
    int warp=threadIdx.x>>5, lane=threadIdx.x&31;
    int gw=blockIdx.x*WJ+warp;
    if (gw>=NU*MM) return;
    int u=gw/MM, i=gw%MM;
    float* A=sh[warp]; float* V=A+625;
    int k,pr,pc,gi; patch_info(i,k,pr,pc,gi);
    const float* cov=g_cov+u*625;
    if (gi==0){
        float sm4[16], av[16], vv[16];
        #pragma unroll
        for (int e=0;e<16;e++){
            int r=e>>2, c=e&3;
            int ir=(pr+(r>>1))*5+pc+(r&1);
            int ic=(pr+(c>>1))*5+pc+(c&1);
            sm4[e]=cov[ir*25+ic]+g_E11[r*16+c];
        }
        eigh4_plain(sm4,av,vv);
        for (int e=lane;e<625;e+=32){
            int a=e/25, b=e%25;
            float val=0.f;
            if (a==b) val=(a<4)? av[a*5] : g_mu[a-4];
            else if (a<4 && b>=4){
                #pragma unroll
                for (int t=0;t<4;t++) val+=vv[t*4+a]*g_CZ[t*21+(b-4)];
            } else if (b<4 && a>=4){
                #pragma unroll
                for (int t=0;t<4;t++) val+=vv[t*4+b]*g_CZ[t*21+(a-4)];
            }
            A[e]=val;
        }
        for (int e=lane;e<625;e+=32){
            int a=e/25, j=e%25;
            float val;
            if (j<4){
                val=0.f;
                #pragma unroll
                for (int i2=0;i2<4;i2++) val+=sv0[i2*25+a]*vv[i2*4+j];
            } else val=g_P2[a*21+(j-4)];
            V[e]=val;
        }
        __syncwarp();
        warp_jacobi(A,V,25,sched25,25,13,scb[warp],ssb[warp],spq[warp],true);
    } else if (gi==1){
        logv_mid<9>(A,V,1,sv1,cov,k,pr,pc,sched9,sched25,scb[warp],ssb[warp],spq[warp]);
    } else if (gi==2){
        logv_mid<16>(A,V,2,sv2,cov,k,pr,pc,sched16,sched25,scb[warp],ssb[warp],spq[warp]);
    } else {
        for (int e=lane;e<625;e+=32) A[e]=cov[e]+g_E11g3[e];
        for (int e=lane;e<625;e+=32){
            int a=e/25, j=e%25;
            V[e]=sv3[j*25+a];
        }
        __syncwarp();
        warp_jacobi(A,V,25,sched25,25,13,scb[warp],ssb[warp],spq[warp],true);
    }
    if (lane<25) sd[warp][lane]=logf(fmaxf(A[lane*26],1e-9f));
    __syncwarp();
    for (int e=lane;e<625;e+=32) A[e]=V[e]*sd[warp][e%25];
    __syncwarp();
    float* out=g_V+(size_t)gw*325;
    for (int r=lane;r<325;r+=32){
        int ij=tri25[r]; int a=ij>>8, b=ij&255;
        float acc=0.f;
        #pragma unroll 5
        for (int kx=0;kx<25;kx++) acc+=A[a*25+kx]*V[b*25+kx];
        out[r]=acc;
    }
}

__global__ void k_att1(){
    __shared__ float sh[WJ][1250];
    __shared__ float scb[WJ][16], ssb[WJ][16];
    __shared__ int spq[WJ][16];
    __shared__ float sd[WJ][25];
    __shared__ unsigned short sched[325];
    __shared__ unsigned short tri25[325];
    __shared__ float pp[WJ][30];
    sched_init(sched,25);
    tri_init(tri25,25);
    int warp=threadIdx.x>>5, lane=threadIdx.x&31;
    int u=blockIdx.x*WJ+warp;
    if (u>=NU) return;
    float* A=sh[warp]; float* V=A+625;
    if (lane<30) pp[warp][lane]=g_p[u*30+lane];
    __syncwarp();
    const float* Vb=g_V+(size_t)u*30*325;
    for (int r=lane;r<325;r+=32){
        float acc=0.f;
        #pragma unroll 5
        for (int i=0;i<30;i++) acc+=pp[warp][i]*Vb[(size_t)i*325+r];
        int ij=tri25[r]; int a=ij>>8, b=ij&255;
        A[a*25+b]=acc; A[b*25+a]=acc;
    }
    __syncwarp();
    warp_jacobi(A,V,25,sched,25,13,scb[warp],ssb[warp],spq[warp],false);
    if (lane<25) sd[warp][lane]=fmaxf(expf(A[lane*26]),1e-4f);
    __syncwarp();
    for (int e=lane;e<625;e+=32) A[e]=V[e]*sd[warp][e%25];
    __syncwarp();
    float* dst=g_xm+u*625;
    for (int r=lane;r<325;r+=32){
        int ij=tri25[r]; int a=ij>>8, b=ij&255;
        float acc=0.f;
        #pragma unroll 5
        for (int kx=0;kx<25;kx++) acc+=A[a*25+kx]*V[b*25+kx];
        dst[a*25+b]=acc; dst[b*25+a]=acc;
    }
}

__global__ void k_s2log(const float* __restrict__ mq,const float* __restrict__ mk,
                        const float* __restrict__ mv){
    __shared__ float sh[WJ][1250];
    __shared__ float scb[WJ][16], ssb[WJ][16];
    __shared__ int spq[WJ][16];
    __shared__ float sd[WJ][18];
    __shared__ unsigned short sched[153];
    __shared__ unsigned short tri18[171];
    sched_init(sched,18);
    tri_init(tri18,18);
    int warp=threadIdx.x>>5, lane=threadIdx.x&31;
    int id=blockIdx.x*WJ+warp;
    if (id>=BB*9) return;
    int b=id/9, rem=id%9, t=rem/3, c=rem%3;
    float* A=sh[warp]; float* V=A+625;
    const float* W=(c==0?mq:(c==1?mk:mv));
    const float* X=g_xm+(b*3+t)*625;
    for (int e=lane;e<450;e+=32){
        int r=e/18, a=e%18;
        float acc=0.f;
        for (int cc=0;cc<25;cc++) acc+=X[r*25+cc]*W[cc*18+a];
        V[e]=acc;
    }
    __syncwarp();
    for (int e=lane;e<324;e+=32){
        int a=e/18, bb=e%18;
        float acc=0.f;
        for (int r=0;r<25;r++) acc+=W[r*18+a]*V[r*18+bb];
        A[e]=acc;
    }
    __syncwarp();
    warp_jacobi(A,V,18,sched,17,9,scb[warp],ssb[warp],spq[warp],false);
    if (lane<18) sd[warp][lane]=logf(fmaxf(A[lane*19],1e-9f));
    __syncwarp();
    for (int e=lane;e<324;e+=32) A[e]=V[e]*sd[warp][e%18];
    __syncwarp();
    float* dst=(c==0?g_logQ2:(c==1?g_logK2:g_logV2))+(b*3+t)*324;
    for (int r=lane;r<171;r+=32){
        int ij=tri18[r]; int a=ij>>8, bb=ij&255;
        float acc=0.f;
        #pragma unroll 6
        for (int kx=0;kx<18;kx++) acc+=A[a*18+kx]*V[bb*18+kx];
        dst[a*18+bb]=acc; dst[bb*18+a]=acc;
    }
}

__global__ void k_s2att(){
    __shared__ float sh[WJ][1250];
    __shared__ float scb[WJ][16], ssb[WJ][16];
    __shared__ int spq[WJ][16];
    __shared__ float sd[WJ][18];
    __shared__ unsigned short sched[153];
    __shared__ unsigned short tri18[171];
    sched_init(sched,18);
    tri_init(tri18,18);
    int warp=threadIdx.x>>5, lane=threadIdx.x&31;
    int id=blockIdx.x*WJ+warp;
    if (id>=BB*3) return;
    int b=id/3, j=id%3;
    float* A=sh[warp]; float* V=A+625;
    const float* lQ=g_logQ2+(b*3+j)*324;
    float qn=0.f;
    for (int e=lane;e<324;e+=32){ float v=lQ[e]; qn+=v*v; }
    qn=warp_sum(qn);
    float p3[3];
    #pragma unroll
    for (int i=0;i<3;i++){
        const float* lK=g_logK2+(b*3+i)*324;
        float kn=0.f, cr=0.f;
        for (int e=lane;e<324;e+=32){ float a=lK[e], q=lQ[e]; kn+=a*a; cr+=a*q; }
        kn=warp_sum(kn); cr=warp_sum(cr);
        float E=fmaxf(kn+qn-2.f*cr,0.f);
        p3[i]=1.f/(1.f+log1pf(E));
    }
    float mx=fmaxf(p3[0],fmaxf(p3[1],p3[2]));
    float sm=0.f;
    #pragma unroll
    for (int i=0;i<3;i++){ p3[i]=expf(p3[i]-mx); sm+=p3[i]; }
    #pragma unroll
    for (int i=0;i<3;i++) p3[i]/=sm;
    for (int e=lane;e<324;e+=32){
        float acc=0.f;
        #pragma unroll
        for (int i=0;i<3;i++) acc+=p3[i]*g_logV2[(b*3+i)*324+e];
        A[e]=acc;
    }
    __syncwarp();
    warp_jacobi(A,V,18,sched,17,9,scb[warp],ssb[warp],spq[warp],false);
    if (lane<18) sd[warp][lane]=fmaxf(A[lane*19],-9.210340371976184f);
    __syncwarp();
    for (int e=lane;e<324;e+=32) A[e]=V[e]*sd[warp][e%18];
    __syncwarp();
    for (int r=lane;r<171;r+=32){
        int ij=tri18[r]; int ii=ij>>8, jj=ij&255;
        float acc=0.f;
        #pragma unroll 6
        for (int kx=0;kx<18;kx++) acc+=A[ii*18+kx]*V[jj*18+kx];
        float coef=(ii==jj)?1.f:1.41421356237309515f;
        g_feat[b*513 + j*171 + r]=acc*coef;
    }
}

__global__ void k_head(const float* __restrict__ lw, const float* __restrict__ lb,
                       float* __restrict__ out){
    int b=blockIdx.x; int o=threadIdx.x>>5; int lane=threadIdx.x&31;
    if (o>=4) return;
    float acc=0.f;
    for (int r=lane;r<513;r+=32) acc+=g_feat[b*513+r]*lw[o*513+r];
    acc=warp_sum(acc);
    if (lane==0) out[b*4+o]=acc+lb[o];
}

extern "C" void kernel_launch(void* const* d_in, const int* in_sizes, int n_in,
                              void* d_out, int out_size){
    const float* x   =(const float*)d_in[0];
    const float* c1w =(const float*)d_in[1];
    const float* c1b =(const float*)d_in[2];
    const float* bn1g=(const float*)d_in[3];
    const float* bn1b=(const float*)d_in[4];
    const float* bn1m=(const float*)d_in[5];
    const float* bn1v=(const float*)d_in[6];
    const float* c2w =(const float*)d_in[7];
    const float* c2b =(const float*)d_in[8];
    const float* bn2g=(const float*)d_in[9];
    const float* bn2b=(const float*)d_in[10];
    const float* bn2m=(const float*)d_in[11];
    const float* bn2v=(const float*)d_in[12];
    bool inter = (in_sizes[14]==16);
    const float *sk[4], *sv[4], *sq3p;
    if (inter){
        sq3p=(const float*)d_in[13+3*3];
        for (int g=0; g<4; g++){
            sk[g]=(const float*)d_in[14+3*g];
            sv[g]=(const float*)d_in[15+3*g];
        }
    } else {
        sq3p=(const float*)d_in[16];
        for (int g=0; g<4; g++){
            sk[g]=(const float*)d_in[17+g];
            sv[g]=(const float*)d_in[21+g];
        }
    }
    const float* mq=(const float*)d_in[25];
    const float* mk=(const float*)d_in[26];
    const float* mv=(const float*)d_in[27];
    const float* lw=(const float*)d_in[28];
    const float* lb=(const float*)d_in[29];

    k_prep <<<1,128>>>(sv[0],sv[1],sv[2],sv[3]);
    k_conv1<<<dim3(8,BB),128>>>(x,c1w,c1b,bn1g,bn1b,bn1m,bn1v);
    k_conv2<<<dim3(8,BB),128>>>(c2w,c2b,bn2g,bn2b,bn2m,bn2v);
    k_cov  <<<NU,256>>>();
    k_qk   <<<NU/4,128>>>(sk[0],sk[1],sk[2],sk[3],sq3p);
    k_logV <<<(NU*MM+WJ-1)/WJ,WJ*32>>>(sv[0],sv[1],sv[2],sv[3]);
    k_att1 <<<(NU+WJ-1)/WJ,WJ*32>>>();
    k_s2log<<<(BB*9+WJ-1)/WJ,WJ*32>>>(mq,mk,mv);
    k_s2att<<<(BB*3+WJ-1)/WJ,WJ*32>>>();
    k_head <<<BB,128>>>(lw,lb,(float*)d_out);
}

// round 14
// speedup vs baseline: 1.4547x; 1.0058x over previous
#include <cuda_runtime.h>
#include <cuda_bf16.h>

#define BB   256
#define T0   1000
#define T1C  1001
#define C1   22
#define C2   25
#define NEP  3
#define NU   (BB*NEP)
#define MM   30
#define TW   128
#define WJ   8

__device__ float g_y1  [BB*C1*T0];
__device__ float g_sig [BB*C2*T1C];
__device__ float g_cov [NU*625];
__device__ float g_V   [NU*MM*325];
__device__ float g_p   [NU*MM];
__device__ float g_xm  [NU*625];
__device__ float g_logQ2[BB*3*324];
__device__ float g_logK2[BB*3*324];
__device__ float g_logV2[BB*3*324];
__device__ float g_feat [BB*513];
__device__ float g_P2 [3*525];
__device__ float g_CZ [3*336];
__device__ float g_E11[3*256];
__device__ float g_mu [3*21];
__device__ float g_E11g3[625];

__device__ __forceinline__ float warp_sum(float v){
    #pragma unroll
    for (int o=16;o;o>>=1) v += __shfl_xor_sync(0xffffffffu, v, o);
    return v;
}

__device__ __forceinline__ void patch_info(int i, int&k, int&pr, int&pc, int&gi){
    if (i<16){ gi=0;k=2;pr=i/4;pc=i%4; }
    else if (i<25){ gi=1;k=3;int p=i-16;pr=p/3;pc=p%3; }
    else if (i<29){ gi=2;k=4;int p=i-25;pr=p/2;pc=p%2; }
    else { gi=3;k=5;pr=0;pc=0; }
}

__device__ void sched_init(unsigned short* sched, int n){
    int m=(n+1)&~1, P=m>>1, R=m-1;
    for (int idx=threadIdx.x; idx<R*P; idx+=blockDim.x){
        int r=idx/P, i=idx%P;
        int j=m-1-i;
        int a=(i==0)?0:(1+(r+i-1)%(m-1));
        int b=1+(r+j-1)%(m-1);
        int p=min(a,b), q=max(a,b);
        sched[idx]=(q<n)? (unsigned short)((p<<8)|q) : (unsigned short)0xFFFF;
    }
    __syncthreads();
}
__device__ void sched_init_w(unsigned short* sched, int n){
    int lane=threadIdx.x&31;
    int m=(n+1)&~1, P=m>>1, R=m-1;
    for (int idx=lane; idx<R*P; idx+=32){
        int r=idx/P, i=idx%P;
        int j=m-1-i;
        int a=(i==0)?0:(1+(r+i-1)%(m-1));
        int b=1+(r+j-1)%(m-1);
        int p=min(a,b), q=max(a,b);
        sched[idx]=(q<n)? (unsigned short)((p<<8)|q) : (unsigned short)0xFFFF;
    }
    __syncwarp();
}
__device__ void tri_init(unsigned short* tri, int n){
    for (int r=threadIdx.x; r<n*(n+1)/2; r+=blockDim.x){
        int i=0, rr=r;
        while (rr>=n-i){ rr-=n-i; i++; }
        tri[r]=(unsigned short)((i<<8)|(i+rr));
    }
    __syncthreads();
}

// Tournament-batched Jacobi (threshold relaxed to 1e-12).
__device__ void warp_jacobi(float* A, float* Vv, int n, const unsigned short* sched,
                            int R, int P, float* cb, float* sb, int* pqb, bool preV){
    int lane=threadIdx.x&31;
    if (!preV) for (int e=lane;e<n*n;e+=32) Vv[e]=((e%(n+1))==0)?1.f:0.f;
    float nrm=0.f;
    for (int e=lane;e<n*n;e+=32) nrm+=A[e]*A[e];
    nrm=warp_sum(nrm);
    float thr=nrm*1e-12f+1e-38f;
    __syncwarp();
    for (int sweep=0;sweep<24;sweep++){
        int any=0;
        for (int r=0;r<R;r++){
            bool act=false; int pq=0; float c0=1.f,s0=0.f;
            if (lane<P){
                pq=sched[r*P+lane];
                if (pq!=0xFFFF){
                    int p=pq>>8, q=pq&255;
                    float apq=A[p*n+q];
                    if (apq*apq>thr){
                        act=true;
                        float app=A[p*n+p], aqq=A[q*n+q];
                        float tau=(aqq-app)/(2.f*apq);
                        float t=copysignf(1.f,tau)/(fabsf(tau)+sqrtf(1.f+tau*tau));
                        c0=rsqrtf(1.f+t*t); s0=t*c0;
                    }
                }
            }
            unsigned msk=__ballot_sync(0xffffffffu,act);
            int cnt=__popc(msk);
            if (!cnt) continue;
            any=1;
            if (act){
                int pos=__popc(msk&((1u<<lane)-1u));
                pqb[pos]=pq; cb[pos]=c0; sb[pos]=s0;
            }
            __syncwarp();
            if (lane<n){
                for (int i=0;i<cnt;i++){
                    int pq2=pqb[i]; int p=pq2>>8, q=pq2&255;
                    float cc=cb[i], ss=sb[i];
                    float akp=A[lane*n+p], akq=A[lane*n+q];
                    A[lane*n+p]=cc*akp-ss*akq; A[lane*n+q]=ss*akp+cc*akq;
                    float vkp=Vv[lane*n+p], vkq=Vv[lane*n+q];
                    Vv[lane*n+p]=cc*vkp-ss*vkq; Vv[lane*n+q]=ss*vkp+cc*vkq;
                }
            }
            __syncwarp();
            if (lane<n){
                for (int i=0;i<cnt;i++){
                    int pq2=pqb[i]; int p=pq2>>8, q=pq2&255;
                    float cc=cb[i], ss=sb[i];
                    float apk=A[p*n+lane], aqk=A[q*n+lane];
                    A[p*n+lane]=cc*apk-ss*aqk; A[q*n+lane]=ss*apk+cc*aqk;
                }
            }
            __syncwarp();
        }
        if (!any) break;
    }
    __syncwarp();
}

__device__ __forceinline__ void eigh4_plain(const float* m, float* a, float* v){
    #pragma unroll
    for (int i=0;i<16;i++){ a[i]=m[i]; v[i]=((i%5)==0)?1.f:0.f; }
    float nrm=0.f;
    #pragma unroll
    for (int i=0;i<16;i++) nrm+=a[i]*a[i];
    float thr=nrm*1e-15f+1e-38f;
    for (int sw=0;sw<10;sw++){
        bool rot=false;
        #pragma unroll
        for (int p=0;p<3;p++){
            #pragma unroll
            for (int q=p+1;q<4;q++){
                float apq=a[p*4+q];
                if (apq*apq>thr){
                    rot=true;
                    float app=a[p*5], aqq=a[q*5];
                    float tau=(aqq-app)/(2.f*apq);
                    float t=copysignf(1.f,tau)/(fabsf(tau)+sqrtf(1.f+tau*tau));
                    float c=rsqrtf(1.f+t*t), s=t*c;
                    #pragma unroll
                    for (int k2=0;k2<4;k2++){
                        float akp=a[k2*4+p], akq=a[k2*4+q];
                        a[k2*4+p]=c*akp-s*akq; a[k2*4+q]=s*akp+c*akq;
                        float vkp=v[k2*4+p], vkq=v[k2*4+q];
                        v[k2*4+p]=c*vkp-s*vkq; v[k2*4+q]=s*vkp+c*vkq;
                    }
                    #pragma unroll
                    for (int k2=0;k2<4;k2++){
                        float apk=a[p*4+k2], aqk=a[q*4+k2];
                        a[p*4+k2]=c*apk-s*aqk; a[q*4+k2]=s*apk+c*aqk;
                    }
                }
            }
        }
        if (!rot) break;
    }
}

__device__ __forceinline__ void eigh4_log(const float* m, float* out){
    float a[16], v[16];
    eigh4_plain(m,a,v);
    float fw[4];
    #pragma unroll
    for (int i=0;i<4;i++) fw[i]=logf(fmaxf(a[i*5],1e-9f));
    #pragma unroll
    for (int i=0;i<16;i++){
        int r2=i/4, c2=i%4;
        float acc=0.f;
        #pragma unroll
        for (int k2=0;k2<4;k2++) acc+=v[r2*4+k2]*fw[k2]*v[c2*4+k2];
        out[i]=acc;
    }
}

__global__ void k_prep(const float* __restrict__ sv0,const float* __restrict__ sv1,
                       const float* __restrict__ sv2,const float* __restrict__ sv3){
    __shared__ float shp[3][1560];
    __shared__ unsigned short ssch[3][231];
    __shared__ float cbs[3][16], sbs[3][16];
    __shared__ int pqs[3][16];
    int warp=threadIdx.x>>5, lane=threadIdx.x&31;
    if (warp==3){
        for (int e=lane;e<625;e+=32){
            int i=e/25, j=e%25;
            float acc=0.f;
            for (int a=0;a<25;a++) acc+=sv3[i*25+a]*(4e-6f*(1.f+a))*sv3[j*25+a];
            g_E11g3[e]=acc;
        }
        return;
    }
    const float* sv=(warp==0?sv0:warp==1?sv1:sv2);
    const int KAP=(warp==0?4:warp==1?9:16);
    const int R=25-KAP;
    float* Wp=shp[warp];
    float* F =Wp+525;
    float* Z =F+441;
    float* Bm=Z+441;
    for (int e=lane;e<KAP*KAP;e+=32){
        int i=e/KAP, j=e%KAP;
        float acc=0.f;
        for (int a=0;a<25;a++) acc+=sv[i*25+a]*(4e-6f*(1.f+a))*sv[j*25+a];
        g_E11[warp*256+i*16+j]=acc;
    }
    __syncwarp();
    int rc=0;
    for (int cand=0; cand<25 && rc<R; cand++){
        float v=(lane==cand)?1.f:0.f;
        for (int pass=0;pass<2;pass++){
            for (int i=0;i<KAP;i++){
                float w=(lane<25)?sv[i*25+lane]:0.f;
                float d=warp_sum(v*w); v-=d*w;
            }
            for (int i=0;i<rc;i++){
                float w=(lane<25)?Wp[i*25+lane]:0.f;
                float d=warp_sum(v*w); v-=d*w;
            }
        }
        float nn=warp_sum(v*v);
        if (nn>1e-4f){
            float inv=rsqrtf(nn);
            if (lane<25) Wp[rc*25+lane]=v*inv;
            rc++;
        }
        __syncwarp();
    }
    for (int e=lane;e<R*R;e+=32){
        int m2=e/R, n2=e%R;
        float acc=0.f;
        for (int a=0;a<25;a++) acc+=Wp[m2*25+a]*(4e-6f*(1.f+a))*Wp[n2*25+a];
        F[e]=acc;
    }
    sched_init_w(ssch[warp],R);
    int m=(R+1)&~1;
    warp_jacobi(F,Z,R,ssch[warp],m-1,m>>1,cbs[warp],sbs[warp],pqs[warp],false);
    if (lane<R) g_mu[warp*21+lane]=F[lane*(R+1)];
    __syncwarp();
    for (int e=lane;e<25*R;e+=32){
        int a=e/R, m2=e%R;
        float acc=0.f;
        for (int t=0;t<R;t++) acc+=Wp[t*25+a]*Z[t*R+m2];
        g_P2[warp*525+a*21+m2]=acc;
    }
    for (int e=lane;e<KAP*R;e+=32){
        int i=e/R, t=e%R;
        float acc=0.f;
        for (int a=0;a<25;a++) acc+=sv[i*25+a]*(4e-6f*(1.f+a))*Wp[t*25+a];
        Bm[e]=acc;
    }
    __syncwarp();
    for (int e=lane;e<KAP*R;e+=32){
        int i=e/R, m2=e%R;
        float acc=0.f;
        for (int t=0;t<R;t++) acc+=Bm[i*R+t]*Z[t*R+m2];
        g_CZ[warp*336+i*21+m2]=acc;
    }
}

__global__ void k_conv1(const float* __restrict__ x, const float* __restrict__ w,
                        const float* __restrict__ cb, const float* __restrict__ bg,
                        const float* __restrict__ bb, const float* __restrict__ bm,
                        const float* __restrict__ bv){
    __shared__ float sw[C1*C1];
    __shared__ float ssc[C1], ssh[C1];
    int tid=threadIdx.x;
    for (int i=tid;i<C1*C1;i+=blockDim.x) sw[i]=w[i];
    if (tid<C1){
        float sc=bg[tid]*rsqrtf(bv[tid]+1e-5f);
        ssc[tid]=sc; ssh[tid]=bb[tid]+(cb[tid]-bm[tid])*sc;
    }
    __syncthreads();
    int b=blockIdx.y; int t=blockIdx.x*blockDim.x+tid;
    if (t>=T0) return;
    float xv[C1];
    #pragma unroll
    for (int h=0;h<C1;h++) xv[h]=x[(b*C1+h)*T0+t];
    #pragma unroll 1
    for (int o=0;o<C1;o++){
        float acc=0.f;
        #pragma unroll
        for (int h=0;h<C1;h++) acc+=xv[h]*sw[o*C1+h];
        g_y1[(b*C1+o)*T0+t]=acc*ssc[o]+ssh[o];
    }
}

__global__ void k_conv2(const float* __restrict__ w2, const float* __restrict__ cb,
                        const float* __restrict__ bg, const float* __restrict__ bb,
                        const float* __restrict__ bm, const float* __restrict__ bv){
    __shared__ float sw[C2*C1*12];
    __shared__ float sy[C1*(TW+12)];
    __shared__ float ssc[C2], ssh[C2];
    int tid=threadIdx.x;
    for (int i=tid;i<C2*C1*12;i+=TW) sw[i]=w2[i];
    if (tid<C2){
        float sc=bg[tid]*rsqrtf(bv[tid]+1e-5f);
        ssc[tid]=sc; ssh[tid]=bb[tid]+(cb[tid]-bm[tid])*sc;
    }
    int b=blockIdx.y; int t0=blockIdx.x*TW;
    for (int i=tid;i<C1*(TW+12);i+=TW){
        int c=i/(TW+12), u=i%(TW+12);
        int tt=t0-6+u;
        sy[i]=(tt>=0 && tt<T0)? g_y1[(b*C1+c)*T0+tt] : 0.f;
    }
    __syncthreads();
    int t=t0+tid;
    if (t>=T1C) return;
    float acc[C2];
    #pragma unroll
    for (int o=0;o<C2;o++) acc[o]=0.f;
    for (int c=0;c<C1;c++){
        float yv[12];
        #pragma unroll
        for (int kk=0;kk<12;kk++) yv[kk]=sy[c*(TW+12)+tid+kk];
        #pragma unroll 1
        for (int o=0;o<C2;o++){
            float a=acc[o];
            #pragma unroll
            for (int kk=0;kk<12;kk++) a+=yv[kk]*sw[(o*C1+c)*12+kk];
            acc[o]=a;
        }
    }
    #pragma unroll 1
    for (int o=0;o<C2;o++) g_sig[(b*C2+o)*T1C+t]=acc[o]*ssc[o]+ssh[o];
}

__global__ void k_cov(){
    __shared__ float s[C2*334];
    __shared__ float cc[325];
    __shared__ float tr_s;
    int u=blockIdx.x, b=u/NEP, e=u%NEP;
    int off=e*334; int L=(e==2)?333:334;
    int tid=threadIdx.x;
    for (int idx=tid; idx<C2*L; idx+=256){
        int c=idx/L, t=idx%L;
        s[c*334+t]=g_sig[(b*C2+c)*T1C+off+t];
    }
    __syncthreads();
    if (tid<C2){
        float acc=0.f;
        for (int t=0;t<L;t++) acc+=s[tid*334+t];
        float mean=acc/(float)L;
        for (int t=0;t<L;t++) s[tid*334+t]-=mean;
    }
    __syncthreads();
    for (int r=tid;r<325;r+=256){
        int i=0, rr=r;
        while (rr>=C2-i){ rr-=C2-i; i++; }
        int j=i+rr;
        float acc=0.f;
        for (int t=0;t<L;t++) acc+=s[i*334+t]*s[j*334+t];
        cc[r]=acc/(float)(L-1);
    }
    __syncthreads();
    if (tid==0){
        float tr=0.f;
        for (int i=0;i<C2;i++) tr+=cc[i*C2 - i*(i-1)/2];
        tr_s=tr;
    }
    __syncthreads();
    float inv=1.f/tr_s;
    float* dst=g_cov+u*625;
    for (int e2=tid;e2<625;e2+=256){
        int i=e2/25, j=e2%25;
        int ii=min(i,j), jj=max(i,j);
        float v=cc[ii*C2 - ii*(ii-1)/2 + (jj-ii)]*inv;
        if (i==j) v+=1e-5f;
        dst[e2]=v;
    }
}

__global__ void k_qk(const float* __restrict__ sk0,const float* __restrict__ sk1,
                     const float* __restrict__ sk2,const float* __restrict__ sk3,
                     const float* __restrict__ sq3){
    __shared__ float scov[4][625];
    __shared__ float sK[4][31*16];
    int warp=threadIdx.x>>5, lane=threadIdx.x&31;
    int u=blockIdx.x*4+warp;
    const float* cov=g_cov+u*625;
    for (int e=lane;e<625;e+=32) scov[warp][e]=cov[e];
    __syncwarp();
    if (lane<31){
        int i=(lane==30)?29:lane;
        int k,pr,pc,gi; patch_info(i,k,pr,pc,gi);
        int kk=k*k;
        const float* W=(lane==30)? sq3 : (gi==0?sk0:gi==1?sk1:gi==2?sk2:sk3);
        float Km[16];
        #pragma unroll
        for (int e=0;e<16;e++) Km[e]=0.f;
        for (int c=0;c<kk;c++){
            int ic=(pr+c/k)*5 + pc + c%k;
            float sa[4]={0.f,0.f,0.f,0.f};
            for (int r=0;r<kk;r++){
                int ir=(pr+r/k)*5 + pc + r%k;
                float xx=scov[warp][ir*25+ic];
                #pragma unroll
                for (int a=0;a<4;a++) sa[a]+=W[r*4+a]*xx;
            }
            #pragma unroll
            for (int a=0;a<4;a++)
                #pragma unroll
                for (int b2=0;b2<4;b2++) Km[a*4+b2]+=sa[a]*W[c*4+b2];
        }
        #pragma unroll
        for (int d=0;d<4;d++) Km[d*5]+=2.5e-5f*(1.f+d);
        float logm[16];
        eigh4_log(Km, logm);
        #pragma unroll
        for (int e=0;e<16;e++) sK[warp][lane*16+e]=logm[e];
    }
    __syncwarp();
    float scval=-1e30f;
    if (lane<30){
        float kn=0.f,cr=0.f,qn=0.f;
        #pragma unroll
        for (int e=0;e<16;e++){
            float a=sK[warp][lane*16+e], q=sK[warp][30*16+e];
            kn+=a*a; cr+=a*q; qn+=q*q;
        }
        float E=fmaxf(kn+qn-2.f*cr,0.f);
        scval=1.f/(1.f+log1pf(E));
    }
    float mx=scval;
    #pragma unroll
    for (int o=16;o;o>>=1) mx=fmaxf(mx,__shfl_xor_sync(0xffffffffu,mx,o));
    float ev=(lane<30)?expf(scval-mx):0.f;
    float sm=warp_sum(ev);
    if (lane<30) g_p[u*30+lane]=ev/sm;
}

template<int KAP>
__device__ void logv_mid(float* A, float* V, int gi, const float* __restrict__ sv,
                         const float* __restrict__ cov, int k, int pr, int pc,
                         const unsigned short* schedS, const unsigned short* sched25,
                         float* cb, float* sb, int* pqb){
    const int lane=threadIdx.x&31;
    const int R=25-KAP;
    const float* E11=g_E11+gi*256;
    const float* mu =g_mu +gi*21;
    const float* P2 =g_P2 +gi*525;
    const float* CZ =g_CZ +gi*336;
    for (int e=lane;e<KAP*KAP;e+=32){
        int r=e/KAP, c=e%KAP;
        int ir=(pr+r/k)*5+pc+r%k;
        int ic=(pr+c/k)*5+pc+c%k;
        A[e]=cov[ir*25+ic]+E11[r*16+c];
    }
    __syncwarp();
    const int m=(KAP+1)&~1;
    warp_jacobi(A,V,KAP,schedS,m-1,m>>1,cb,sb,pqb,false);
    float Yc[KAP];
    float lam=0.f;
    if (lane<KAP){
        #pragma unroll
        for (int t=0;t<KAP;t++) Yc[t]=V[t*KAP+lane];
        lam=A[lane*(KAP+1)];
    }
    __syncwarp();
    for (int e=lane;e<625;e+=32) A[e]=0.f;
    __syncwarp();
    if (lane<KAP){
        A[lane*26]=lam;
        #pragma unroll 1
        for (int mm2=0;mm2<R;mm2++){
            float g=0.f;
            #pragma unroll
            for (int t=0;t<KAP;t++) g+=Yc[t]*CZ[t*21+mm2];
            A[lane*25+(KAP+mm2)]=g;
            A[(KAP+mm2)*25+lane]=g;
        }
    } else if (lane<25){
        A[lane*26]=mu[lane-KAP];
    }
    for (int e=lane;e<25*R;e+=32){
        int a=e/R, mm2=e%R;
        V[a*25+KAP+mm2]=P2[a*21+mm2];
    }
    __syncwarp();
    if (lane<KAP){
        #pragma unroll 1
        for (int a=0;a<25;a++){
            float val=0.f;
            #pragma unroll
            for (int i2=0;i2<KAP;i2++) val+=sv[i2*25+a]*Yc[i2];
            V[a*25+lane]=val;
        }
    }
    __syncwarp();
    warp_jacobi(A,V,25,sched25,25,13,cb,sb,pqb,true);
}

__global__ void k_logV(const float* __restrict__ sv0,const float* __restrict__ sv1,
                       const float* __restrict__ sv2,const float* __restrict__ sv3){
    __shared__ float sh[WJ][1250];
    __shared__ float scb[WJ][16], ssb[WJ][16];
    __shared__ int spq[WJ][16];
    __shared__ float sd[WJ][25];
    __shared__ unsigned short sched25[325];
    __shared__ unsigned short sched9[45];
    __shared__ unsigned short sched16[120];
    __shared__ unsigned short tri25[325];
    sched_init(sched25,25);
    sched_init(sched9,9);
    sched_init(sched16,16);
    tri_init(tri25,25);
    int warp=threadIdx.x>>5, lane=threadIdx.x&31;
    int gw=blockIdx.x*WJ+warp;
    if (gw>=NU*MM) return;
    int u=gw/MM, i=gw%MM;
    float* A=sh[warp]; float* V=A+625;
    int k,pr,pc,gi; patch_info(i,k,pr,pc,gi);
    const float* cov=g_cov+u*625;
    if (gi==0){
        float sm4[16], av[16], vv[16];
        #pragma unroll
        for (int e=0;e<16;e++){
            int r=e>>2, c=e&3;
            int ir=(pr+(r>>1))*5+pc+(r&1);
            int ic=(pr+(c>>1))*5+pc+(c&1);
            sm4[e]=cov[ir*25+ic]+g_E11[r*16+c];
        }
        eigh4_plain(sm4,av,vv);
        for (int e=lane;e<625;e+=32){
            int a=e/25, b=e%25;
            float val=0.f;
            if (a==b) val=(a<4)? av[a*5] : g_mu[a-4];
            else if (a<4 && b>=4){
                #pragma unroll
                for (int t=0;t<4;t++) val+=vv[t*4+a]*g_CZ[t*21+(b-4)];
            } else if (b<4 && a>=4){
                #pragma unroll
                for (int t=0;t<4;t++) val+=vv[t*4+b]*g_CZ[t*21+(a-4)];
            }
            A[e]=val;
        }
        for (int e=lane;e<625;e+=32){
            int a=e/25, j=e%25;
            float val;
            if (j<4){
                val=0.f;
                #pragma unroll
                for (int i2=0;i2<4;i2++) val+=sv0[i2*25+a]*vv[i2*4+j];
            } else val=g_P2[a*21+(j-4)];
            V[e]=val;
        }
        __syncwarp();
        warp_jacobi(A,V,25,sched25,25,13,scb[warp],ssb[warp],spq[warp],true);
    } else if (gi==1){
        logv_mid<9>(A,V,1,sv1,cov,k,pr,pc,sched9,sched25,scb[warp],ssb[warp],spq[warp]);
    } else if (gi==2){
        logv_mid<16>(A,V,2,sv2,cov,k,pr,pc,sched16,sched25,scb[warp],ssb[warp],spq[warp]);
    } else {
        for (int e=lane;e<625;e+=32) A[e]=cov[e]+g_E11g3[e];
        for (int e=lane;e<625;e+=32){
            int a=e/25, j=e%25;
            V[e]=sv3[j*25+a];
        }
        __syncwarp();
        warp_jacobi(A,V,25,sched25,25,13,scb[warp],ssb[warp],spq[warp],true);
    }
    if (lane<25) sd[warp][lane]=logf(fmaxf(A[lane*26],1e-9f));
    __syncwarp();
    for (int e=lane;e<625;e+=32) A[e]=V[e]*sd[warp][e%25];
    __syncwarp();
    float* out=g_V+(size_t)gw*325;
    for (int r=lane;r<325;r+=32){
        int ij=tri25[r]; int a=ij>>8, b=ij&255;
        float acc=0.f;
        #pragma unroll 5
        for (int kx=0;kx<25;kx++) acc+=A[a*25+kx]*V[b*25+kx];
        out[r]=acc;
    }
}

__global__ void k_att1(){
    __shared__ float sh[WJ][1250];
    __shared__ float scb[WJ][16], ssb[WJ][16];
    __shared__ int spq[WJ][16];
    __shared__ float sd[WJ][25];
    __shared__ unsigned short sched[325];
    __shared__ unsigned short tri25[325];
    __shared__ float pp[WJ][30];
    sched_init(sched,25);
    tri_init(tri25,25);
    int warp=threadIdx.x>>5, lane=threadIdx.x&31;
    int u=blockIdx.x*WJ+warp;
    if (u>=NU) return;
    float* A=sh[warp]; float* V=A+625;
    if (lane<30) pp[warp][lane]=g_p[u*30+lane];
    __syncwarp();
    const float* Vb=g_V+(size_t)u*30*325;
    for (int r=lane;r<325;r+=32){
        float acc=0.f;
        #pragma unroll 5
        for (int i=0;i<30;i++) acc+=pp[warp][i]*Vb[(size_t)i*325+r];
        int ij=tri25[r]; int a=ij>>8, b=ij&255;
        A[a*25+b]=acc; A[b*25+a]=acc;
    }
    __syncwarp();
    warp_jacobi(A,V,25,sched,25,13,scb[warp],ssb[warp],spq[warp],false);
    if (lane<25) sd[warp][lane]=fmaxf(expf(A[lane*26]),1e-4f);
    __syncwarp();
    for (int e=lane;e<625;e+=32) A[e]=V[e]*sd[warp][e%25];
    __syncwarp();
    float* dst=g_xm+u*625;
    for (int r=lane;r<325;r+=32){
        int ij=tri25[r]; int a=ij>>8, b=ij&255;
        float acc=0.f;
        #pragma unroll 5
        for (int kx=0;kx<25;kx++) acc+=A[a*25+kx]*V[b*25+kx];
        dst[a*25+b]=acc; dst[b*25+a]=acc;
    }
}

__global__ void k_s2log(const float* __restrict__ mq,const float* __restrict__ mk,
                        const float* __restrict__ mv){
    __shared__ float sh[WJ][784];
    __shared__ float scb[WJ][16], ssb[WJ][16];
    __shared__ int spq[WJ][16];
    __shared__ float sd[WJ][18];
    __shared__ unsigned short sched[153];
    __shared__ unsigned short tri18[171];
    sched_init(sched,18);
    tri_init(tri18,18);
    int warp=threadIdx.x>>5, lane=threadIdx.x&31;
    int id=blockIdx.x*WJ+warp;
    if (id>=BB*9) return;
    int b=id/9, rem=id%9, t=rem/3, c=rem%3;
    float* A=sh[warp]; float* V=A+324;  // V region: 460 floats (450 temp, then 324 vectors)
    const float* W=(c==0?mq:(c==1?mk:mv));
    const float* X=g_xm+(b*3+t)*625;
    for (int e=lane;e<450;e+=32){
        int r=e/18, a=e%18;
        float acc=0.f;
        for (int cc=0;cc<25;cc++) acc+=X[r*25+cc]*W[cc*18+a];
        V[e]=acc;
    }
    __syncwarp();
    for (int e=lane;e<324;e+=32){
        int a=e/18, bb=e%18;
        float acc=0.f;
        for (int r=0;r<25;r++) acc+=W[r*18+a]*V[r*18+bb];
        A[e]=acc;
    }
    __syncwarp();
    warp_jacobi(A,V,18,sched,17,9,scb[warp],ssb[warp],spq[warp],false);
    if (lane<18) sd[warp][lane]=logf(fmaxf(A[lane*19],1e-9f));
    __syncwarp();
    for (int e=lane;e<324;e+=32) A[e]=V[e]*sd[warp][e%18];
    __syncwarp();
    float* dst=(c==0?g_logQ2:(c==1?g_logK2:g_logV2))+(b*3+t)*324;
    for (int r=lane;r<171;r+=32){
        int ij=tri18[r]; int a=ij>>8, bb=ij&255;
        float acc=0.f;
        #pragma unroll 6
        for (int kx=0;kx<18;kx++) acc+=A[a*18+kx]*V[bb*18+kx];
        dst[a*18+bb]=acc; dst[bb*18+a]=acc;
    }
}

__global__ void k_s2att(){
    __shared__ float sh[WJ][656];
    __shared__ float scb[WJ][16], ssb[WJ][16];
    __shared__ int spq[WJ][16];
    __shared__ float sd[WJ][18];
    __shared__ unsigned short sched[153];
    __shared__ unsigned short tri18[171];
    sched_init(sched,18);
    tri_init(tri18,18);
    int warp=threadIdx.x>>5, lane=threadIdx.x&31;
    int id=blockIdx.x*WJ+warp;
    if (id>=BB*3) return;
    int b=id/3, j=id%3;
    float* A=sh[warp]; float* V=A+328;
    const float* lQ=g_logQ2+(b*3+j)*324;
    float qn=0.f;
    for (int e=lane;e<324;e+=32){ float v=lQ[e]; qn+=v*v; }
    qn=warp_sum(qn);
    float p3[3];
    #pragma unroll
    for (int i=0;i<3;i++){
        const float* lK=g_logK2+(b*3+i)*324;
        float kn=0.f, cr=0.f;
        for (int e=lane;e<324;e+=32){ float a=lK[e], q=lQ[e]; kn+=a*a; cr+=a*q; }
        kn=warp_sum(kn); cr=warp_sum(cr);
        float E=fmaxf(kn+qn-2.f*cr,0.f);
        p3[i]=1.f/(1.f+log1pf(E));
    }
    float mx=fmaxf(p3[0],fmaxf(p3[1],p3[2]));
    float sm=0.f;
    #pragma unroll
    for (int i=0;i<3;i++){ p3[i]=expf(p3[i]-mx); sm+=p3[i]; }
    #pragma unroll
    for (int i=0;i<3;i++) p3[i]/=sm;
    for (int e=lane;e<324;e+=32){
        float acc=0.f;
        #pragma unroll
        for (int i=0;i<3;i++) acc+=p3[i]*g_logV2[(b*3+i)*324+e];
        A[e]=acc;
    }
    __syncwarp();
    warp_jacobi(A,V,18,sched,17,9,scb[warp],ssb[warp],spq[warp],false);
    if (lane<18) sd[warp][lane]=fmaxf(A[lane*19],-9.210340371976184f);
    __syncwarp();
    for (int e=lane;e<324;e+=32) A[e]=V[e]*sd[warp][e%18];
    __syncwarp();
    for (int r=lane;r<171;r+=32){
        int ij=tri18[r]; int ii=ij>>8, jj=ij&255;
        float acc=0.f;
        #pragma unroll 6
        for (int kx=0;kx<18;kx++) acc+=A[ii*18+kx]*V[jj*18+kx];
        float coef=(ii==jj)?1.f:1.41421356237309515f;
        g_feat[b*513 + j*171 + r]=acc*coef;
    }
}

__global__ void k_head(const float* __restrict__ lw, const float* __restrict__ lb,
                       float* __restrict__ out){
    int b=blockIdx.x; int o=threadIdx.x>>5; int lane=threadIdx.x&31;
    if (o>=4) return;
    float acc=0.f;
    for (int r=lane;r<513;r+=32) acc+=g_feat[b*513+r]*lw[o*513+r];
    acc=warp_sum(acc);
    if (lane==0) out[b*4+o]=acc+lb[o];
}

extern "C" void kernel_launch(void* const* d_in, const int* in_sizes, int n_in,
                              void* d_out, int out_size){
    const float* x   =(const float*)d_in[0];
    const float* c1w =(const float*)d_in[1];
    const float* c1b =(const float*)d_in[2];
    const float* bn1g=(const float*)d_in[3];
    const float* bn1b=(const float*)d_in[4];
    const float* bn1m=(const float*)d_in[5];
    const float* bn1v=(const float*)d_in[6];
    const float* c2w =(const float*)d_in[7];
    const float* c2b =(const float*)d_in[8];
    const float* bn2g=(const float*)d_in[9];
    const float* bn2b=(const float*)d_in[10];
    const float* bn2m=(const float*)d_in[11];
    const float* bn2v=(const float*)d_in[12];
    bool inter = (in_sizes[14]==16);
    const float *sk[4], *sv[4], *sq3p;
    if (inter){
        sq3p=(const float*)d_in[13+3*3];
        for (int g=0; g<4; g++){
            sk[g]=(const float*)d_in[14+3*g];
            sv[g]=(const float*)d_in[15+3*g];
        }
    } else {
        sq3p=(const float*)d_in[16];
        for (int g=0; g<4; g++){
            sk[g]=(const float*)d_in[17+g];
            sv[g]=(const float*)d_in[21+g];
        }
    }
    const float* mq=(const float*)d_in[25];
    const float* mk=(const float*)d_in[26];
    const float* mv=(const float*)d_in[27];
    const float* lw=(const float*)d_in[28];
    const float* lb=(const float*)d_in[29];

    k_prep <<<1,128>>>(sv[0],sv[1],sv[2],sv[3]);
    k_conv1<<<dim3(8,BB),128>>>(x,c1w,c1b,bn1g,bn1b,bn1m,bn1v);
    k_conv2<<<dim3(8,BB),128>>>(c2w,c2b,bn2g,bn2b,bn2m,bn2v);
    k_cov  <<<NU,256>>>();
    k_qk   <<<NU/4,128>>>(sk[0],sk[1],sk[2],sk[3],sq3p);
    k_logV <<<(NU*MM+WJ-1)/WJ,WJ*32>>>(sv[0],sv[1],sv[2],sv[3]);
    k_att1 <<<(NU+WJ-1)/WJ,WJ*32>>>();
    k_s2log<<<(BB*9+WJ-1)/WJ,WJ*32>>>(mq,mk,mv);
    k_s2att<<<(BB*3+WJ-1)/WJ,WJ*32>>>();
    k_head <<<BB,128>>>(lw,lb,(float*)d_out);
}